// round 12
// baseline (speedup 1.0000x reference)
#include <cuda_runtime.h>
#include <cuda_fp16.h>
#include <stdint.h>

#define NB 16
#define TDIM 1024
#define DEMB 1024

// ---------------- scratch (__device__ globals, allocation-free rule) --------
__device__ __half g_Q[(size_t)NB * TDIM * DEMB];
__device__ __half g_K[(size_t)NB * TDIM * DEMB];
__device__ __half g_V[(size_t)NB * TDIM * DEMB];
__device__ __half g_P[(size_t)NB * TDIM * TDIM];
__device__ float  g_S[(size_t)NB * TDIM * TDIM];
__device__ __half g_Wqh[DEMB * DEMB];
__device__ __half g_Wkh[DEMB * DEMB];
__device__ __half g_Wvh[DEMB * DEMB];

// ---------------- smem: 3 stages; A 16KB/stage, B 16KB/stage (96KB) --------
constexpr int STG = 16384;            // 128 rows x 128B (or 64 rows x 256B for V)
constexpr int SB_OFF = 3 * STG;
constexpr int SMEM_BYTES = 6 * STG + 1024;

#define CP_CG(dst, src) \
    asm volatile("cp.async.cg.shared.global [%0], [%1], 16;" :: "r"(dst), "l"(src))
#define CP_COMMIT() asm volatile("cp.async.commit_group;" ::: "memory")
#define CP_WAIT(n)  asm volatile("cp.async.wait_group %0;" :: "n"(n) : "memory")

__device__ __forceinline__ unsigned packh2(float x, float y) {
    __half2 h = __floats2half2_rn(x, y);
    return *(unsigned*)&h;
}

__device__ __forceinline__ void ldsm4(unsigned& r0, unsigned& r1, unsigned& r2, unsigned& r3,
                                      unsigned a) {
    asm volatile("ldmatrix.sync.aligned.m8n8.x4.shared.b16 {%0,%1,%2,%3}, [%4];"
                 : "=r"(r0), "=r"(r1), "=r"(r2), "=r"(r3) : "r"(a));
}
__device__ __forceinline__ void ldsm4t(unsigned& r0, unsigned& r1, unsigned& r2, unsigned& r3,
                                       unsigned a) {
    asm volatile("ldmatrix.sync.aligned.m8n8.x4.trans.shared.b16 {%0,%1,%2,%3}, [%4];"
                 : "=r"(r0), "=r"(r1), "=r"(r2), "=r"(r3) : "r"(a));
}
__device__ __forceinline__ void mma16816(float* c, const unsigned* a, const unsigned* b) {
    asm volatile(
        "mma.sync.aligned.m16n8k16.row.col.f32.f16.f16.f32 "
        "{%0,%1,%2,%3},{%4,%5,%6,%7},{%8,%9},{%0,%1,%2,%3};"
        : "+f"(c[0]), "+f"(c[1]), "+f"(c[2]), "+f"(c[3])
        : "r"(a[0]), "r"(a[1]), "r"(a[2]), "r"(a[3]), "r"(b[0]), "r"(b[1]));
}

// stage rows x 64 halves (k-major, 128B rows), XOR swizzle; 4 chunks/call
__device__ __forceinline__ void cp_km(unsigned dst, const char* src, size_t rowBytes,
                                      int r, int cg) {
    const char* p = src + (size_t)r * rowBytes + cg * 16;
    unsigned d = dst + r * 128;
#pragma unroll
    for (int j = 0; j < 4; j++) {
        unsigned c = cg + j;
        CP_CG(d + ((c ^ (r & 7)) << 4), p + j * 16);
    }
}

// stage V chunk: 64 k-rows x 128 n-halves (256B rows); 4 of 16 chunks/thread
__device__ __forceinline__ void cp_vrow(unsigned dst, const char* src, size_t rowBytes,
                                        int k, int cg) {
    const char* p = src + (size_t)k * rowBytes + cg * 16;
    unsigned d = dst + k * 256;
#pragma unroll
    for (int j = 0; j < 4; j++) {
        unsigned c = cg + j;
        CP_CG(d + ((c ^ (k & 7)) << 4), p + j * 16);
    }
}

// load 64B-worth of f16 (4 chunks) from f32 source row, converting
__device__ __forceinline__ void lda32(uint4* v, const char* src, int r, int cg) {
    const char* p = src + (size_t)r * (DEMB * 4) + cg * 32;
#pragma unroll
    for (int j = 0; j < 4; j++) {
        float4 a = *(const float4*)(p + j * 32);
        float4 b = *(const float4*)(p + j * 32 + 16);
        v[j].x = packh2(a.x, a.y); v[j].y = packh2(a.z, a.w);
        v[j].z = packh2(b.x, b.y); v[j].w = packh2(b.z, b.w);
    }
}
__device__ __forceinline__ void sts_a(unsigned dst, const uint4* v, int r, int cg) {
    unsigned d = dst + r * 128;
#pragma unroll
    for (int j = 0; j < 4; j++) {
        unsigned c = cg + j;
        asm volatile("st.shared.v4.b32 [%0], {%1,%2,%3,%4};"
                     :: "r"(d + ((c ^ (r & 7)) << 4)),
                        "r"(v[j].x), "r"(v[j].y), "r"(v[j].z), "r"(v[j].w));
    }
}

// ============================================================================
// Shared NT gemm body (f16 A in gmem via cp.async): block 128x128, 256 thr.
// ============================================================================
template <typename TC>
__device__ __forceinline__ void gemm_nt_body(
    const char* pa, const char* pb, const float* bias, TC* C,
    int N, int K, float alpha, int bx, int by, unsigned sbase)
{
    int tid = threadIdx.x, warp = tid >> 5, lane = tid & 31;
    int wr = warp & 3, wc = warp >> 2;
    int qr = lane >> 2, rr = lane & 3;
    int r = tid >> 1, cg = (tid & 1) * 4;
    size_t rowB = (size_t)K * 2;

    float acc[2][8][4];
#pragma unroll
    for (int mt = 0; mt < 2; mt++)
#pragma unroll
        for (int nt = 0; nt < 8; nt++)
#pragma unroll
            for (int i = 0; i < 4; i++) acc[mt][nt][i] = 0.f;

    const int nIter = K / 64;

    cp_km(sbase, pa, rowB, r, cg);
    cp_km(sbase + SB_OFF, pb, rowB, r, cg);
    CP_COMMIT();
    cp_km(sbase + STG, pa + 128, rowB, r, cg);
    cp_km(sbase + SB_OFF + STG, pb + 128, rowB, r, cg);
    CP_COMMIT();

    for (int it = 0; it < nIter; ++it) {
        if (it + 2 < nIter) {
            int s = (it + 2) % 3;
            cp_km(sbase + s * STG, pa + (size_t)(it + 2) * 128, rowB, r, cg);
            cp_km(sbase + SB_OFF + s * STG, pb + (size_t)(it + 2) * 128, rowB, r, cg);
            CP_COMMIT();
            CP_WAIT(2);
        } else if (it + 1 < nIter) {
            CP_WAIT(1);
        } else {
            CP_WAIT(0);
        }
        __syncthreads();

        unsigned sa = sbase + (it % 3) * STG;
        unsigned sb = sbase + SB_OFF + (it % 3) * STG;
#pragma unroll
        for (int ks = 0; ks < 4; ks++) {
            int ch = ks * 2 + (lane >> 4);
            unsigned af[2][4], bf[8][2];
#pragma unroll
            for (int mt = 0; mt < 2; mt++) {
                int row = wr * 32 + mt * 16 + (lane & 15);
                ldsm4(af[mt][0], af[mt][1], af[mt][2], af[mt][3],
                      sa + row * 128 + ((ch ^ (row & 7)) << 4));
            }
#pragma unroll
            for (int ng = 0; ng < 4; ng++) {
                int row = wc * 64 + ng * 16 + (lane & 15);
                unsigned r0, r1, r2, r3;
                ldsm4(r0, r1, r2, r3, sb + row * 128 + ((ch ^ (row & 7)) << 4));
                bf[2 * ng][0] = r0; bf[2 * ng][1] = r2;
                bf[2 * ng + 1][0] = r1; bf[2 * ng + 1][1] = r3;
            }
#pragma unroll
            for (int mt = 0; mt < 2; mt++)
#pragma unroll
                for (int nt = 0; nt < 8; nt++)
                    mma16816(acc[mt][nt], af[mt], bf[nt]);
        }
        __syncthreads();
    }

#pragma unroll
    for (int mt = 0; mt < 2; mt++) {
#pragma unroll
        for (int nt = 0; nt < 8; nt++) {
            int row = by * 128 + wr * 32 + mt * 16 + qr;
            int col = bx * 128 + wc * 64 + nt * 8 + rr * 2;
            float b0 = bias ? bias[col] : 0.f;
            float b1 = bias ? bias[col + 1] : 0.f;
            float x0 = acc[mt][nt][0] * alpha + b0;
            float x1 = acc[mt][nt][1] * alpha + b1;
            float x2 = acc[mt][nt][2] * alpha + b0;
            float x3 = acc[mt][nt][3] * alpha + b1;
            if constexpr (sizeof(TC) == 2) {
                *(unsigned*)&C[(size_t)row * N + col] = packh2(x0, x1);
                *(unsigned*)&C[(size_t)(row + 8) * N + col] = packh2(x2, x3);
            } else {
                float2 v;
                v.x = x0; v.y = x1;
                *(float2*)&C[(size_t)row * N + col] = v;
                v.x = x2; v.y = x3;
                *(float2*)&C[(size_t)(row + 8) * N + col] = v;
            }
        }
    }
}

// ============================================================================
// Batched projections reading X as f32 directly (convert during A-staging).
// z in {0,1,2} selects (X, W, bias, out). W is pre-converted f16 (cp.async).
// ============================================================================
__global__ __launch_bounds__(256, 2) void hgemm_proj3f(
    const float* __restrict__ X0, const float* __restrict__ X1,
    const float* __restrict__ X2,
    const __half* __restrict__ W0, const __half* __restrict__ W1,
    const __half* __restrict__ W2,
    const float* __restrict__ b0, const float* __restrict__ b1,
    const float* __restrict__ b2,
    __half* __restrict__ C0, __half* __restrict__ C1, __half* __restrict__ C2)
{
    extern __shared__ char raw[];
    char* smem = (char*)(((uintptr_t)raw + 1023) & ~(uintptr_t)1023);
    unsigned sbase = (unsigned)__cvta_generic_to_shared(smem);

    int bx = blockIdx.x, by = blockIdx.y, bz = blockIdx.z;
    const float* X = (bz == 0) ? X0 : (bz == 1) ? X1 : X2;
    const __half* W = (bz == 0) ? W0 : (bz == 1) ? W1 : W2;
    const float* bias = (bz == 0) ? b0 : (bz == 1) ? b1 : b2;
    __half* C = (bz == 0) ? C0 : (bz == 1) ? C1 : C2;

    int tid = threadIdx.x, warp = tid >> 5, lane = tid & 31;
    int wr = warp & 3, wc = warp >> 2;
    int qr = lane >> 2, rr = lane & 3;
    int r = tid >> 1, cg = (tid & 1) * 4;

    const char* pa = (const char*)(X + (size_t)(by * 128) * DEMB);  // f32 rows
    const char* pb = (const char*)(W + (size_t)(bx * 128) * DEMB);  // f16 rows

    float acc[2][8][4];
#pragma unroll
    for (int mt = 0; mt < 2; mt++)
#pragma unroll
        for (int nt = 0; nt < 8; nt++)
#pragma unroll
            for (int i = 0; i < 4; i++) acc[mt][nt][i] = 0.f;

    const int nIter = DEMB / 64;   // 16; per-iter A advance = 64 f32 = 256B

    // prologue: A stages 0,1 staged synchronously; B via cp.async
    {
        uint4 av[4];
        lda32(av, pa, r, cg);
        sts_a(sbase, av, r, cg);
        lda32(av, pa + 256, r, cg);
        sts_a(sbase + STG, av, r, cg);
    }
    cp_km(sbase + SB_OFF, pb, DEMB * 2, r, cg);
    CP_COMMIT();
    cp_km(sbase + SB_OFF + STG, pb + 128, DEMB * 2, r, cg);
    CP_COMMIT();

    for (int it = 0; it < nIter; ++it) {
        uint4 av[4];
        bool pre = (it + 2 < nIter);
        if (pre) {
            int s = (it + 2) % 3;
            cp_km(sbase + SB_OFF + s * STG, pb + (size_t)(it + 2) * 128,
                  DEMB * 2, r, cg);
            CP_COMMIT();
            lda32(av, pa + (size_t)(it + 2) * 256, r, cg);   // overlaps wait
            CP_WAIT(2);
        } else if (it + 1 < nIter) {
            CP_WAIT(1);
        } else {
            CP_WAIT(0);
        }
        __syncthreads();
        if (pre) sts_a(sbase + ((it + 2) % 3) * STG, av, r, cg);

        unsigned sa = sbase + (it % 3) * STG;
        unsigned sb = sbase + SB_OFF + (it % 3) * STG;
#pragma unroll
        for (int ks = 0; ks < 4; ks++) {
            int ch = ks * 2 + (lane >> 4);
            unsigned af[2][4], bf[8][2];
#pragma unroll
            for (int mt = 0; mt < 2; mt++) {
                int row = wr * 32 + mt * 16 + (lane & 15);
                ldsm4(af[mt][0], af[mt][1], af[mt][2], af[mt][3],
                      sa + row * 128 + ((ch ^ (row & 7)) << 4));
            }
#pragma unroll
            for (int ng = 0; ng < 4; ng++) {
                int row = wc * 64 + ng * 16 + (lane & 15);
                unsigned r0, r1, r2, r3;
                ldsm4(r0, r1, r2, r3, sb + row * 128 + ((ch ^ (row & 7)) << 4));
                bf[2 * ng][0] = r0; bf[2 * ng][1] = r2;
                bf[2 * ng + 1][0] = r1; bf[2 * ng + 1][1] = r3;
            }
#pragma unroll
            for (int mt = 0; mt < 2; mt++)
#pragma unroll
                for (int nt = 0; nt < 8; nt++)
                    mma16816(acc[mt][nt], af[mt], bf[nt]);
        }
        __syncthreads();
    }

#pragma unroll
    for (int mt = 0; mt < 2; mt++) {
#pragma unroll
        for (int nt = 0; nt < 8; nt++) {
            int row = by * 128 + wr * 32 + mt * 16 + qr;
            int col = bx * 128 + wc * 64 + nt * 8 + rr * 2;
            float b0 = bias[col];
            float b1 = bias[col + 1];
            *(unsigned*)&C[(size_t)row * DEMB + col] =
                packh2(acc[mt][nt][0] + b0, acc[mt][nt][1] + b1);
            *(unsigned*)&C[(size_t)(row + 8) * DEMB + col] =
                packh2(acc[mt][nt][2] + b0, acc[mt][nt][3] + b1);
        }
    }
}

// ============================================================================
// QK^T: batched over z, causal block skip. C = f32 S.
// ============================================================================
__global__ __launch_bounds__(256, 2) void hgemm_qk(
    const __half* __restrict__ Q, const __half* __restrict__ Kd,
    float* __restrict__ S, float alpha)
{
    int bx = blockIdx.x, by = blockIdx.y, bz = blockIdx.z;
    if (bx > by) return;

    extern __shared__ char raw[];
    char* smem = (char*)(((uintptr_t)raw + 1023) & ~(uintptr_t)1023);
    unsigned sbase = (unsigned)__cvta_generic_to_shared(smem);

    const char* pa = (const char*)(Q + (size_t)bz * TDIM * DEMB + (size_t)(by * 128) * DEMB);
    const char* pb = (const char*)(Kd + (size_t)bz * TDIM * DEMB + (size_t)(bx * 128) * DEMB);
    float* C = S + (size_t)bz * TDIM * TDIM;
    gemm_nt_body<float>(pa, pb, nullptr, C, TDIM, DEMB, alpha, bx, by, sbase);
}

// ============================================================================
// PV: O[m,n] = sum_k P[m,k]*V[k,n]; block 128x128, warps 4x2 of 32x64.
// ============================================================================
__global__ __launch_bounds__(256, 2) void hgemm_pv(
    const __half* __restrict__ P, const __half* __restrict__ V,
    float* __restrict__ O)
{
    int bx = blockIdx.x, by = blockIdx.y, bz = blockIdx.z;

    extern __shared__ char raw[];
    char* smem = (char*)(((uintptr_t)raw + 1023) & ~(uintptr_t)1023);
    unsigned sbase = (unsigned)__cvta_generic_to_shared(smem);

    int tid = threadIdx.x, warp = tid >> 5, lane = tid & 31;
    int wr = warp & 3, wc = warp >> 2;
    int qr = lane >> 2, rr = lane & 3;
    int r = tid >> 1, cg = (tid & 1) * 4;
    int vk = tid >> 2, vg = (tid & 3) * 4;

    const char* pa = (const char*)(P + (size_t)bz * TDIM * TDIM + (size_t)(by * 128) * TDIM);
    const char* pv = (const char*)(V + (size_t)bz * TDIM * DEMB + bx * 128);
    float* C = O + (size_t)bz * TDIM * DEMB;
    size_t rowA = (size_t)TDIM * 2;
    size_t rowV = (size_t)DEMB * 2;

    float acc[2][8][4];
#pragma unroll
    for (int mt = 0; mt < 2; mt++)
#pragma unroll
        for (int nt = 0; nt < 8; nt++)
#pragma unroll
            for (int i = 0; i < 4; i++) acc[mt][nt][i] = 0.f;

    const int nIter = (by + 1) * 2;

    cp_km(sbase, pa, rowA, r, cg);
    cp_vrow(sbase + SB_OFF, pv, rowV, vk, vg);
    CP_COMMIT();
    cp_km(sbase + STG, pa + 128, rowA, r, cg);
    cp_vrow(sbase + SB_OFF + STG, pv + 64 * rowV, rowV, vk, vg);
    CP_COMMIT();

    for (int it = 0; it < nIter; ++it) {
        if (it + 2 < nIter) {
            int s = (it + 2) % 3;
            cp_km(sbase + s * STG, pa + (size_t)(it + 2) * 128, rowA, r, cg);
            cp_vrow(sbase + SB_OFF + s * STG, pv + (size_t)(it + 2) * 64 * rowV, rowV, vk, vg);
            CP_COMMIT();
            CP_WAIT(2);
        } else if (it + 1 < nIter) {
            CP_WAIT(1);
        } else {
            CP_WAIT(0);
        }
        __syncthreads();

        unsigned sa = sbase + (it % 3) * STG;
        unsigned sb = sbase + SB_OFF + (it % 3) * STG;
#pragma unroll
        for (int ks = 0; ks < 4; ks++) {
            int ch = ks * 2 + (lane >> 4);
            unsigned af[2][4], bf[8][2];
#pragma unroll
            for (int mt = 0; mt < 2; mt++) {
                int row = wr * 32 + mt * 16 + (lane & 15);
                ldsm4(af[mt][0], af[mt][1], af[mt][2], af[mt][3],
                      sa + row * 128 + ((ch ^ (row & 7)) << 4));
            }
#pragma unroll
            for (int ng = 0; ng < 4; ng++) {
                int krow = ks * 16 + (lane & 15);
                int cb = (wc * 64 + ng * 16) >> 3;
                int vch = cb + (lane >> 4);
                unsigned r0, r1, r2, r3;
                ldsm4t(r0, r1, r2, r3, sb + krow * 256 + ((vch ^ (krow & 7)) << 4));
                bf[2 * ng][0] = r0; bf[2 * ng][1] = r1;
                bf[2 * ng + 1][0] = r2; bf[2 * ng + 1][1] = r3;
            }
#pragma unroll
            for (int mt = 0; mt < 2; mt++)
#pragma unroll
                for (int nt = 0; nt < 8; nt++)
                    mma16816(acc[mt][nt], af[mt], bf[nt]);
        }
        __syncthreads();
    }

#pragma unroll
    for (int mt = 0; mt < 2; mt++) {
#pragma unroll
        for (int nt = 0; nt < 8; nt++) {
            int row = by * 128 + wr * 32 + mt * 16 + qr;
            int col = bx * 128 + wc * 64 + nt * 8 + rr * 2;
            float2 v;
            v.x = acc[mt][nt][0]; v.y = acc[mt][nt][1];
            *(float2*)&C[(size_t)row * DEMB + col] = v;
            v.x = acc[mt][nt][2]; v.y = acc[mt][nt][3];
            *(float2*)&C[(size_t)(row + 8) * DEMB + col] = v;
        }
    }
}

// ---------------------------------------------------------------------------
// f32 -> f16 convert of the three W matrices only (24MB traffic)
// ---------------------------------------------------------------------------
__global__ void f2h3w(const float* __restrict__ w0, const float* __restrict__ w1,
                      const float* __restrict__ w2,
                      __half* __restrict__ z0, __half* __restrict__ z1,
                      __half* __restrict__ z2, int n4)
{
    int i = blockIdx.x * blockDim.x + threadIdx.x;
    if (i < n4) {
        float4 a = *(const float4*)(w0 + (size_t)i * 4);
        float4 b = *(const float4*)(w1 + (size_t)i * 4);
        float4 c = *(const float4*)(w2 + (size_t)i * 4);
        uint2 u;
        u.x = packh2(a.x, a.y); u.y = packh2(a.z, a.w);
        *(uint2*)(z0 + (size_t)i * 4) = u;
        u.x = packh2(b.x, b.y); u.y = packh2(b.z, b.w);
        *(uint2*)(z1 + (size_t)i * 4) = u;
        u.x = packh2(c.x, c.y); u.y = packh2(c.z, c.w);
        *(uint2*)(z2 + (size_t)i * 4) = u;
    }
}

// ---------------------------------------------------------------------------
// Causal softmax: f32 S row -> half P row; zero tail. 256 thr x 4 elems.
// ---------------------------------------------------------------------------
__global__ void softmax_causal(const float* __restrict__ S, __half* __restrict__ P)
{
    int q = blockIdx.x, b = blockIdx.y;
    const float* row = S + ((size_t)b * TDIM + q) * TDIM;
    __half* prow = P + ((size_t)b * TDIM + q) * TDIM;
    int len = q + 1;
    int tid = threadIdx.x;
    int lane = tid & 31, warp = tid >> 5;

    __shared__ float sred[8];

    int i0 = tid * 4;
    float4 v = *(const float4*)(row + i0);
    float x[4] = {v.x, v.y, v.z, v.w};
#pragma unroll
    for (int j = 0; j < 4; j++)
        if (i0 + j >= len) x[j] = -1e30f;

    float m = fmaxf(fmaxf(x[0], x[1]), fmaxf(x[2], x[3]));
#pragma unroll
    for (int o = 16; o; o >>= 1) m = fmaxf(m, __shfl_xor_sync(0xffffffffu, m, o));
    if (lane == 0) sred[warp] = m;
    __syncthreads();
    if (tid < 32) {
        float t = (tid < 8) ? sred[tid] : -1e30f;
#pragma unroll
        for (int o = 4; o; o >>= 1) t = fmaxf(t, __shfl_xor_sync(0xffffffffu, t, o));
        if (tid == 0) sred[0] = t;
    }
    __syncthreads();
    m = sred[0];

    float e[4], sum = 0.f;
#pragma unroll
    for (int j = 0; j < 4; j++) {
        e[j] = (i0 + j < len) ? __expf(x[j] - m) : 0.f;
        sum += e[j];
    }
#pragma unroll
    for (int o = 16; o; o >>= 1) sum += __shfl_xor_sync(0xffffffffu, sum, o);
    if (lane == 0) sred[warp] = sum;
    __syncthreads();
    if (tid < 32) {
        float t = (tid < 8) ? sred[tid] : 0.f;
#pragma unroll
        for (int o = 4; o; o >>= 1) t += __shfl_xor_sync(0xffffffffu, t, o);
        if (tid == 0) sred[0] = t;
    }
    __syncthreads();
    float inv = 1.f / sred[0];

    uint2 u;
    u.x = packh2(e[0] * inv, e[1] * inv);
    u.y = packh2(e[2] * inv, e[3] * inv);
    *(uint2*)(prow + i0) = u;
}

extern "C" void kernel_launch(void* const* d_in, const int* in_sizes, int n_in,
                              void* d_out, int out_size)
{
    const float* qx = (const float*)d_in[0];
    const float* kx = (const float*)d_in[1];
    const float* vx = (const float*)d_in[2];
    const float* Wq = (const float*)d_in[3];
    const float* bq = (const float*)d_in[4];
    const float* Wk = (const float*)d_in[5];
    const float* bk = (const float*)d_in[6];
    const float* Wv = (const float*)d_in[7];
    const float* bv = (const float*)d_in[8];
    float* out = (float*)d_out;

    __half *pQ, *pK, *pV, *pP, *pWq, *pWk, *pWv;
    float* pS;
    cudaGetSymbolAddress((void**)&pQ, g_Q);
    cudaGetSymbolAddress((void**)&pK, g_K);
    cudaGetSymbolAddress((void**)&pV, g_V);
    cudaGetSymbolAddress((void**)&pP, g_P);
    cudaGetSymbolAddress((void**)&pS, g_S);
    cudaGetSymbolAddress((void**)&pWq, g_Wqh);
    cudaGetSymbolAddress((void**)&pWk, g_Wkh);
    cudaGetSymbolAddress((void**)&pWv, g_Wvh);

    cudaFuncSetAttribute(hgemm_proj3f,
                         cudaFuncAttributeMaxDynamicSharedMemorySize, SMEM_BYTES);
    cudaFuncSetAttribute(hgemm_qk,
                         cudaFuncAttributeMaxDynamicSharedMemorySize, SMEM_BYTES);
    cudaFuncSetAttribute(hgemm_pv,
                         cudaFuncAttributeMaxDynamicSharedMemorySize, SMEM_BYTES);

    const int NW4 = DEMB * DEMB / 4;        // 256K float4 per W tensor
    f2h3w<<<NW4 / 256, 256>>>(Wq, Wk, Wv, pWq, pWk, pWv, NW4);

    dim3 blk(256);

    // All three projections in ONE launch, X read as f32 directly
    dim3 gproj(DEMB / 128, (NB * TDIM) / 128, 3);
    hgemm_proj3f<<<gproj, blk, SMEM_BYTES>>>(qx, kx, vx, pWq, pWk, pWv,
                                             bq, bk, bv, pQ, pK, pV);

    // S = Q K^T / 32 (blocks above diagonal skipped)
    dim3 gattn(TDIM / 128, TDIM / 128, NB);
    hgemm_qk<<<gattn, blk, SMEM_BYTES>>>(pQ, pK, pS, 0.03125f);

    // softmax: S (f32) -> P (half), zero tail
    softmax_causal<<<dim3(TDIM, NB), 256>>>(pS, pP);

    // O = P V (k clipped at diagonal)
    hgemm_pv<<<gattn, blk, SMEM_BYTES>>>(pP, pV, out);
}

// round 13
// speedup vs baseline: 1.3643x; 1.3643x over previous
#include <cuda_runtime.h>
#include <cuda_fp16.h>
#include <stdint.h>

#define NB 16
#define TDIM 1024
#define DEMB 1024

// ---------------- scratch (__device__ globals, allocation-free rule) --------
__device__ __half g_Q[(size_t)NB * TDIM * DEMB];
__device__ __half g_K[(size_t)NB * TDIM * DEMB];
__device__ __half g_V[(size_t)NB * TDIM * DEMB];
__device__ __half g_P[(size_t)NB * TDIM * TDIM];
__device__ float  g_S[(size_t)NB * TDIM * TDIM];
__device__ __half g_Xq[(size_t)NB * TDIM * DEMB];
__device__ __half g_Xk[(size_t)NB * TDIM * DEMB];
__device__ __half g_Xv[(size_t)NB * TDIM * DEMB];
__device__ __half g_Wqh[DEMB * DEMB];
__device__ __half g_Wkh[DEMB * DEMB];
__device__ __half g_Wvh[DEMB * DEMB];

// ---------------- smem: 3 stages; A 16KB/stage, B 16KB/stage (96KB) --------
constexpr int STG = 16384;            // 128 rows x 128B (or 64 rows x 256B for V)
constexpr int SB_OFF = 3 * STG;
constexpr int SMEM_BYTES = 6 * STG + 1024;

#define CP_CG(dst, src) \
    asm volatile("cp.async.cg.shared.global [%0], [%1], 16;" :: "r"(dst), "l"(src))
#define CP_COMMIT() asm volatile("cp.async.commit_group;" ::: "memory")
#define CP_WAIT(n)  asm volatile("cp.async.wait_group %0;" :: "n"(n) : "memory")

__device__ __forceinline__ unsigned packh2(float x, float y) {
    __half2 h = __floats2half2_rn(x, y);
    return *(unsigned*)&h;
}

__device__ __forceinline__ void ldsm4(unsigned& r0, unsigned& r1, unsigned& r2, unsigned& r3,
                                      unsigned a) {
    asm volatile("ldmatrix.sync.aligned.m8n8.x4.shared.b16 {%0,%1,%2,%3}, [%4];"
                 : "=r"(r0), "=r"(r1), "=r"(r2), "=r"(r3) : "r"(a));
}
__device__ __forceinline__ void ldsm4t(unsigned& r0, unsigned& r1, unsigned& r2, unsigned& r3,
                                       unsigned a) {
    asm volatile("ldmatrix.sync.aligned.m8n8.x4.trans.shared.b16 {%0,%1,%2,%3}, [%4];"
                 : "=r"(r0), "=r"(r1), "=r"(r2), "=r"(r3) : "r"(a));
}
__device__ __forceinline__ void mma16816(float* c, const unsigned* a, const unsigned* b) {
    asm volatile(
        "mma.sync.aligned.m16n8k16.row.col.f32.f16.f16.f32 "
        "{%0,%1,%2,%3},{%4,%5,%6,%7},{%8,%9},{%0,%1,%2,%3};"
        : "+f"(c[0]), "+f"(c[1]), "+f"(c[2]), "+f"(c[3])
        : "r"(a[0]), "r"(a[1]), "r"(a[2]), "r"(a[3]), "r"(b[0]), "r"(b[1]));
}

// stage rows x 64 halves (k-major, 128B rows), XOR swizzle; 4 chunks/call
__device__ __forceinline__ void cp_km(unsigned dst, const char* src, size_t rowBytes,
                                      int r, int cg) {
    const char* p = src + (size_t)r * rowBytes + cg * 16;
    unsigned d = dst + r * 128;
#pragma unroll
    for (int j = 0; j < 4; j++) {
        unsigned c = cg + j;
        CP_CG(d + ((c ^ (r & 7)) << 4), p + j * 16);
    }
}

// stage V chunk: 64 k-rows x 128 n-halves (256B rows); 4 of 16 chunks/thread
__device__ __forceinline__ void cp_vrow(unsigned dst, const char* src, size_t rowBytes,
                                        int k, int cg) {
    const char* p = src + (size_t)k * rowBytes + cg * 16;
    unsigned d = dst + k * 256;
#pragma unroll
    for (int j = 0; j < 4; j++) {
        unsigned c = cg + j;
        CP_CG(d + ((c ^ (k & 7)) << 4), p + j * 16);
    }
}

// ============================================================================
// Shared NT gemm body: block 128x128, 256 threads, warps 4x2 of 32x64.
// A,B half k-major, pa/pb pre-offset to block origin. C pre-offset to batch.
// ============================================================================
template <typename TC>
__device__ __forceinline__ void gemm_nt_body(
    const char* pa, const char* pb, const float* bias, TC* C,
    int N, int K, float alpha, int bx, int by, unsigned sbase)
{
    int tid = threadIdx.x, warp = tid >> 5, lane = tid & 31;
    int wr = warp & 3, wc = warp >> 2;       // 4x2 warps, warp tile 32x64
    int qr = lane >> 2, rr = lane & 3;
    int r = tid >> 1, cg = (tid & 1) * 4;    // staging role
    size_t rowB = (size_t)K * 2;

    float acc[2][8][4];
#pragma unroll
    for (int mt = 0; mt < 2; mt++)
#pragma unroll
        for (int nt = 0; nt < 8; nt++)
#pragma unroll
            for (int i = 0; i < 4; i++) acc[mt][nt][i] = 0.f;

    const int nIter = K / 64;

    cp_km(sbase, pa, rowB, r, cg);
    cp_km(sbase + SB_OFF, pb, rowB, r, cg);
    CP_COMMIT();
    cp_km(sbase + STG, pa + 128, rowB, r, cg);
    cp_km(sbase + SB_OFF + STG, pb + 128, rowB, r, cg);
    CP_COMMIT();

    for (int it = 0; it < nIter; ++it) {
        if (it + 2 < nIter) {
            int s = (it + 2) % 3;
            cp_km(sbase + s * STG, pa + (size_t)(it + 2) * 128, rowB, r, cg);
            cp_km(sbase + SB_OFF + s * STG, pb + (size_t)(it + 2) * 128, rowB, r, cg);
            CP_COMMIT();
            CP_WAIT(2);
        } else if (it + 1 < nIter) {
            CP_WAIT(1);
        } else {
            CP_WAIT(0);
        }
        __syncthreads();

        unsigned sa = sbase + (it % 3) * STG;
        unsigned sb = sbase + SB_OFF + (it % 3) * STG;
#pragma unroll
        for (int ks = 0; ks < 4; ks++) {
            int ch = ks * 2 + (lane >> 4);
            unsigned af[2][4], bf[8][2];
#pragma unroll
            for (int mt = 0; mt < 2; mt++) {
                int row = wr * 32 + mt * 16 + (lane & 15);
                ldsm4(af[mt][0], af[mt][1], af[mt][2], af[mt][3],
                      sa + row * 128 + ((ch ^ (row & 7)) << 4));
            }
#pragma unroll
            for (int ng = 0; ng < 4; ng++) {
                int row = wc * 64 + ng * 16 + (lane & 15);
                unsigned r0, r1, r2, r3;
                ldsm4(r0, r1, r2, r3, sb + row * 128 + ((ch ^ (row & 7)) << 4));
                bf[2 * ng][0] = r0; bf[2 * ng][1] = r2;
                bf[2 * ng + 1][0] = r1; bf[2 * ng + 1][1] = r3;
            }
#pragma unroll
            for (int mt = 0; mt < 2; mt++)
#pragma unroll
                for (int nt = 0; nt < 8; nt++)
                    mma16816(acc[mt][nt], af[mt], bf[nt]);
        }
        __syncthreads();
    }

#pragma unroll
    for (int mt = 0; mt < 2; mt++) {
#pragma unroll
        for (int nt = 0; nt < 8; nt++) {
            int row = by * 128 + wr * 32 + mt * 16 + qr;
            int col = bx * 128 + wc * 64 + nt * 8 + rr * 2;
            float b0 = bias ? bias[col] : 0.f;
            float b1 = bias ? bias[col + 1] : 0.f;
            float x0 = acc[mt][nt][0] * alpha + b0;
            float x1 = acc[mt][nt][1] * alpha + b1;
            float x2 = acc[mt][nt][2] * alpha + b0;
            float x3 = acc[mt][nt][3] * alpha + b1;
            if constexpr (sizeof(TC) == 2) {
                *(unsigned*)&C[(size_t)row * N + col] = packh2(x0, x1);
                *(unsigned*)&C[(size_t)(row + 8) * N + col] = packh2(x2, x3);
            } else {
                float2 v;
                v.x = x0; v.y = x1;
                *(float2*)&C[(size_t)row * N + col] = v;
                v.x = x2; v.y = x3;
                *(float2*)&C[(size_t)(row + 8) * N + col] = v;
            }
        }
    }
}

// ============================================================================
// Batched projections: z in {0,1,2} selects (X, W, bias, out). One launch.
// ============================================================================
__global__ __launch_bounds__(256, 2) void hgemm_proj3(
    const __half* __restrict__ X0, const __half* __restrict__ X1,
    const __half* __restrict__ X2,
    const __half* __restrict__ W0, const __half* __restrict__ W1,
    const __half* __restrict__ W2,
    const float* __restrict__ b0, const float* __restrict__ b1,
    const float* __restrict__ b2,
    __half* __restrict__ C0, __half* __restrict__ C1, __half* __restrict__ C2)
{
    extern __shared__ char raw[];
    char* smem = (char*)(((uintptr_t)raw + 1023) & ~(uintptr_t)1023);
    unsigned sbase = (unsigned)__cvta_generic_to_shared(smem);

    int bx = blockIdx.x, by = blockIdx.y, bz = blockIdx.z;
    const __half* X = (bz == 0) ? X0 : (bz == 1) ? X1 : X2;
    const __half* W = (bz == 0) ? W0 : (bz == 1) ? W1 : W2;
    const float* bias = (bz == 0) ? b0 : (bz == 1) ? b1 : b2;
    __half* C = (bz == 0) ? C0 : (bz == 1) ? C1 : C2;

    const char* pa = (const char*)(X + (size_t)(by * 128) * DEMB);
    const char* pb = (const char*)(W + (size_t)(bx * 128) * DEMB);
    gemm_nt_body<__half>(pa, pb, bias, C, DEMB, DEMB, 1.f, bx, by, sbase);
}

// ============================================================================
// QK^T: batched over z, causal block skip. C = f32 S.
// ============================================================================
__global__ __launch_bounds__(256, 2) void hgemm_qk(
    const __half* __restrict__ Q, const __half* __restrict__ Kd,
    float* __restrict__ S, float alpha)
{
    int bx = blockIdx.x, by = blockIdx.y, bz = blockIdx.z;
    if (bx > by) return;

    extern __shared__ char raw[];
    char* smem = (char*)(((uintptr_t)raw + 1023) & ~(uintptr_t)1023);
    unsigned sbase = (unsigned)__cvta_generic_to_shared(smem);

    const char* pa = (const char*)(Q + (size_t)bz * TDIM * DEMB + (size_t)(by * 128) * DEMB);
    const char* pb = (const char*)(Kd + (size_t)bz * TDIM * DEMB + (size_t)(bx * 128) * DEMB);
    float* C = S + (size_t)bz * TDIM * TDIM;
    gemm_nt_body<float>(pa, pb, nullptr, C, TDIM, DEMB, alpha, bx, by, sbase);
}

// ============================================================================
// PV: O[m,n] = sum_k P[m,k]*V[k,n]; block 128x128, warps 4x2 of 32x64.
// P half k-major; V half row-major [k][n] staged 64x256B. k clipped at diag.
// ============================================================================
__global__ __launch_bounds__(256, 2) void hgemm_pv(
    const __half* __restrict__ P, const __half* __restrict__ V,
    float* __restrict__ O)
{
    int bx = blockIdx.x, by = blockIdx.y, bz = blockIdx.z;

    extern __shared__ char raw[];
    char* smem = (char*)(((uintptr_t)raw + 1023) & ~(uintptr_t)1023);
    unsigned sbase = (unsigned)__cvta_generic_to_shared(smem);

    int tid = threadIdx.x, warp = tid >> 5, lane = tid & 31;
    int wr = warp & 3, wc = warp >> 2;
    int qr = lane >> 2, rr = lane & 3;
    int r = tid >> 1, cg = (tid & 1) * 4;       // P staging
    int vk = tid >> 2, vg = (tid & 3) * 4;      // V staging: 64 rows, 4 thr/row

    const char* pa = (const char*)(P + (size_t)bz * TDIM * TDIM + (size_t)(by * 128) * TDIM);
    const char* pv = (const char*)(V + (size_t)bz * TDIM * DEMB + bx * 128);
    float* C = O + (size_t)bz * TDIM * DEMB;
    size_t rowA = (size_t)TDIM * 2;
    size_t rowV = (size_t)DEMB * 2;

    float acc[2][8][4];
#pragma unroll
    for (int mt = 0; mt < 2; mt++)
#pragma unroll
        for (int nt = 0; nt < 8; nt++)
#pragma unroll
            for (int i = 0; i < 4; i++) acc[mt][nt][i] = 0.f;

    const int nIter = (by + 1) * 2;   // k up to (by+1)*128, BK=64

    cp_km(sbase, pa, rowA, r, cg);
    cp_vrow(sbase + SB_OFF, pv, rowV, vk, vg);
    CP_COMMIT();
    cp_km(sbase + STG, pa + 128, rowA, r, cg);
    cp_vrow(sbase + SB_OFF + STG, pv + 64 * rowV, rowV, vk, vg);
    CP_COMMIT();

    for (int it = 0; it < nIter; ++it) {
        if (it + 2 < nIter) {
            int s = (it + 2) % 3;
            cp_km(sbase + s * STG, pa + (size_t)(it + 2) * 128, rowA, r, cg);
            cp_vrow(sbase + SB_OFF + s * STG, pv + (size_t)(it + 2) * 64 * rowV, rowV, vk, vg);
            CP_COMMIT();
            CP_WAIT(2);
        } else if (it + 1 < nIter) {
            CP_WAIT(1);
        } else {
            CP_WAIT(0);
        }
        __syncthreads();

        unsigned sa = sbase + (it % 3) * STG;
        unsigned sb = sbase + SB_OFF + (it % 3) * STG;
#pragma unroll
        for (int ks = 0; ks < 4; ks++) {
            int ch = ks * 2 + (lane >> 4);
            unsigned af[2][4], bf[8][2];
#pragma unroll
            for (int mt = 0; mt < 2; mt++) {
                int row = wr * 32 + mt * 16 + (lane & 15);
                ldsm4(af[mt][0], af[mt][1], af[mt][2], af[mt][3],
                      sa + row * 128 + ((ch ^ (row & 7)) << 4));
            }
#pragma unroll
            for (int ng = 0; ng < 4; ng++) {
                int krow = ks * 16 + (lane & 15);
                int cb = (wc * 64 + ng * 16) >> 3;
                int vch = cb + (lane >> 4);
                unsigned r0, r1, r2, r3;
                ldsm4t(r0, r1, r2, r3, sb + krow * 256 + ((vch ^ (krow & 7)) << 4));
                bf[2 * ng][0] = r0; bf[2 * ng][1] = r1;
                bf[2 * ng + 1][0] = r2; bf[2 * ng + 1][1] = r3;
            }
#pragma unroll
            for (int mt = 0; mt < 2; mt++)
#pragma unroll
                for (int nt = 0; nt < 8; nt++)
                    mma16816(acc[mt][nt], af[mt], bf[nt]);
        }
        __syncthreads();
    }

#pragma unroll
    for (int mt = 0; mt < 2; mt++) {
#pragma unroll
        for (int nt = 0; nt < 8; nt++) {
            int row = by * 128 + wr * 32 + mt * 16 + qr;
            int col = bx * 128 + wc * 64 + nt * 8 + rr * 2;
            float2 v;
            v.x = acc[mt][nt][0]; v.y = acc[mt][nt][1];
            *(float2*)&C[(size_t)row * DEMB + col] = v;
            v.x = acc[mt][nt][2]; v.y = acc[mt][nt][3];
            *(float2*)&C[(size_t)(row + 8) * DEMB + col] = v;
        }
    }
}

// ---------------------------------------------------------------------------
// Merged f32 -> f16 convert: X triplet (2x ILP) + W triplet folded in.
// ---------------------------------------------------------------------------
__global__ void f2h_all(const float* __restrict__ x0, const float* __restrict__ x1,
                        const float* __restrict__ x2,
                        __half* __restrict__ y0, __half* __restrict__ y1,
                        __half* __restrict__ y2,
                        const float* __restrict__ w0, const float* __restrict__ w1,
                        const float* __restrict__ w2,
                        __half* __restrict__ z0, __half* __restrict__ z1,
                        __half* __restrict__ z2, int nX4, int nW4)
{
    int stride = gridDim.x * blockDim.x;
    int i0 = blockIdx.x * blockDim.x + threadIdx.x;
    if (i0 < nW4) {
        float4 a = *(const float4*)(w0 + (size_t)i0 * 4);
        float4 b = *(const float4*)(w1 + (size_t)i0 * 4);
        float4 c = *(const float4*)(w2 + (size_t)i0 * 4);
        uint2 u;
        u.x = packh2(a.x, a.y); u.y = packh2(a.z, a.w);
        *(uint2*)(z0 + (size_t)i0 * 4) = u;
        u.x = packh2(b.x, b.y); u.y = packh2(b.z, b.w);
        *(uint2*)(z1 + (size_t)i0 * 4) = u;
        u.x = packh2(c.x, c.y); u.y = packh2(c.z, c.w);
        *(uint2*)(z2 + (size_t)i0 * 4) = u;
    }
    for (int i = i0; i < nX4; i += 2 * stride) {
        int i1 = i + stride;
        float4 a0 = *(const float4*)(x0 + (size_t)i * 4);
        float4 b0 = *(const float4*)(x1 + (size_t)i * 4);
        float4 c0 = *(const float4*)(x2 + (size_t)i * 4);
        float4 a1, b1, c1;
        bool has1 = (i1 < nX4);
        if (has1) {
            a1 = *(const float4*)(x0 + (size_t)i1 * 4);
            b1 = *(const float4*)(x1 + (size_t)i1 * 4);
            c1 = *(const float4*)(x2 + (size_t)i1 * 4);
        }
        uint2 u;
        u.x = packh2(a0.x, a0.y); u.y = packh2(a0.z, a0.w);
        *(uint2*)(y0 + (size_t)i * 4) = u;
        u.x = packh2(b0.x, b0.y); u.y = packh2(b0.z, b0.w);
        *(uint2*)(y1 + (size_t)i * 4) = u;
        u.x = packh2(c0.x, c0.y); u.y = packh2(c0.z, c0.w);
        *(uint2*)(y2 + (size_t)i * 4) = u;
        if (has1) {
            u.x = packh2(a1.x, a1.y); u.y = packh2(a1.z, a1.w);
            *(uint2*)(y0 + (size_t)i1 * 4) = u;
            u.x = packh2(b1.x, b1.y); u.y = packh2(b1.z, b1.w);
            *(uint2*)(y1 + (size_t)i1 * 4) = u;
            u.x = packh2(c1.x, c1.y); u.y = packh2(c1.z, c1.w);
            *(uint2*)(y2 + (size_t)i1 * 4) = u;
        }
    }
}

// ---------------------------------------------------------------------------
// Causal softmax: f32 S row -> half P row; zero tail. 256 thr x 4 elems.
// Prefix-skip: lanes fully beyond the diagonal never touch gmem for the load.
// ---------------------------------------------------------------------------
__global__ void softmax_causal(const float* __restrict__ S, __half* __restrict__ P)
{
    int q = blockIdx.x, b = blockIdx.y;
    const float* row = S + ((size_t)b * TDIM + q) * TDIM;
    __half* prow = P + ((size_t)b * TDIM + q) * TDIM;
    int len = q + 1;
    int tid = threadIdx.x;
    int lane = tid & 31, warp = tid >> 5;

    __shared__ float sred[8];

    int i0 = tid * 4;
    float x[4] = {-1e30f, -1e30f, -1e30f, -1e30f};
    if (i0 < len) {
        float4 v = *(const float4*)(row + i0);
        x[0] = v.x; x[1] = v.y; x[2] = v.z; x[3] = v.w;
#pragma unroll
        for (int j = 1; j < 4; j++)
            if (i0 + j >= len) x[j] = -1e30f;
    }

    float m = fmaxf(fmaxf(x[0], x[1]), fmaxf(x[2], x[3]));
#pragma unroll
    for (int o = 16; o; o >>= 1) m = fmaxf(m, __shfl_xor_sync(0xffffffffu, m, o));
    if (lane == 0) sred[warp] = m;
    __syncthreads();
    if (tid < 32) {
        float t = (tid < 8) ? sred[tid] : -1e30f;
#pragma unroll
        for (int o = 4; o; o >>= 1) t = fmaxf(t, __shfl_xor_sync(0xffffffffu, t, o));
        if (tid == 0) sred[0] = t;
    }
    __syncthreads();
    m = sred[0];

    float e[4], sum = 0.f;
#pragma unroll
    for (int j = 0; j < 4; j++) {
        e[j] = (i0 + j < len) ? __expf(x[j] - m) : 0.f;
        sum += e[j];
    }
#pragma unroll
    for (int o = 16; o; o >>= 1) sum += __shfl_xor_sync(0xffffffffu, sum, o);
    if (lane == 0) sred[warp] = sum;
    __syncthreads();
    if (tid < 32) {
        float t = (tid < 8) ? sred[tid] : 0.f;
#pragma unroll
        for (int o = 4; o; o >>= 1) t += __shfl_xor_sync(0xffffffffu, t, o);
        if (tid == 0) sred[0] = t;
    }
    __syncthreads();
    float inv = 1.f / sred[0];

    uint2 u;
    u.x = packh2(e[0] * inv, e[1] * inv);
    u.y = packh2(e[2] * inv, e[3] * inv);
    *(uint2*)(prow + i0) = u;
}

extern "C" void kernel_launch(void* const* d_in, const int* in_sizes, int n_in,
                              void* d_out, int out_size)
{
    const float* qx = (const float*)d_in[0];
    const float* kx = (const float*)d_in[1];
    const float* vx = (const float*)d_in[2];
    const float* Wq = (const float*)d_in[3];
    const float* bq = (const float*)d_in[4];
    const float* Wk = (const float*)d_in[5];
    const float* bk = (const float*)d_in[6];
    const float* Wv = (const float*)d_in[7];
    const float* bv = (const float*)d_in[8];
    float* out = (float*)d_out;

    __half *pQ, *pK, *pV, *pP, *pXq, *pXk, *pXv, *pWq, *pWk, *pWv;
    float* pS;
    cudaGetSymbolAddress((void**)&pQ, g_Q);
    cudaGetSymbolAddress((void**)&pK, g_K);
    cudaGetSymbolAddress((void**)&pV, g_V);
    cudaGetSymbolAddress((void**)&pP, g_P);
    cudaGetSymbolAddress((void**)&pS, g_S);
    cudaGetSymbolAddress((void**)&pXq, g_Xq);
    cudaGetSymbolAddress((void**)&pXk, g_Xk);
    cudaGetSymbolAddress((void**)&pXv, g_Xv);
    cudaGetSymbolAddress((void**)&pWq, g_Wqh);
    cudaGetSymbolAddress((void**)&pWk, g_Wkh);
    cudaGetSymbolAddress((void**)&pWv, g_Wvh);

    cudaFuncSetAttribute(hgemm_proj3,
                         cudaFuncAttributeMaxDynamicSharedMemorySize, SMEM_BYTES);
    cudaFuncSetAttribute(hgemm_qk,
                         cudaFuncAttributeMaxDynamicSharedMemorySize, SMEM_BYTES);
    cudaFuncSetAttribute(hgemm_pv,
                         cudaFuncAttributeMaxDynamicSharedMemorySize, SMEM_BYTES);

    const int NX4 = NB * TDIM * DEMB / 4;   // 4M float4 per X tensor
    const int NW4 = DEMB * DEMB / 4;        // 256K float4 per W tensor
    f2h_all<<<4096, 256>>>(qx, kx, vx, pXq, pXk, pXv,
                           Wq, Wk, Wv, pWq, pWk, pWv, NX4, NW4);

    dim3 blk(256);

    // All three projections in ONE launch (z selects tensor triple)
    dim3 gproj(DEMB / 128, (NB * TDIM) / 128, 3);
    hgemm_proj3<<<gproj, blk, SMEM_BYTES>>>(pXq, pXk, pXv, pWq, pWk, pWv,
                                            bq, bk, bv, pQ, pK, pV);

    // S = Q K^T / 32 (blocks above diagonal skipped)
    dim3 gattn(TDIM / 128, TDIM / 128, NB);
    hgemm_qk<<<gattn, blk, SMEM_BYTES>>>(pQ, pK, pS, 0.03125f);

    // softmax: S (f32) -> P (half), zero tail
    softmax_causal<<<dim3(TDIM, NB), 256>>>(pS, pP);

    // O = P V (k clipped at diagonal)
    hgemm_pv<<<gattn, blk, SMEM_BYTES>>>(pP, pV, out);
}

// round 14
// speedup vs baseline: 1.3804x; 1.0119x over previous
#include <cuda_runtime.h>
#include <cuda_fp16.h>
#include <stdint.h>

#define NB 16
#define TDIM 1024
#define DEMB 1024

// ---------------- scratch (__device__ globals, allocation-free rule) --------
__device__ __half g_Q[(size_t)NB * TDIM * DEMB];
__device__ __half g_K[(size_t)NB * TDIM * DEMB];
__device__ __half g_V[(size_t)NB * TDIM * DEMB];
__device__ __half g_P[(size_t)NB * TDIM * TDIM];
__device__ float  g_S[(size_t)NB * TDIM * TDIM];
__device__ __half g_Xq[(size_t)NB * TDIM * DEMB];
__device__ __half g_Xk[(size_t)NB * TDIM * DEMB];
__device__ __half g_Xv[(size_t)NB * TDIM * DEMB];
__device__ __half g_Wqh[DEMB * DEMB];
__device__ __half g_Wkh[DEMB * DEMB];
__device__ __half g_Wvh[DEMB * DEMB];

// ---------------- smem: 3 stages; A 16KB/stage, B 16KB/stage (96KB) --------
constexpr int STG = 16384;            // 128 rows x 128B (or 64 rows x 256B for V)
constexpr int SB_OFF = 3 * STG;
constexpr int SMEM_BYTES = 6 * STG + 1024;

#define CP_CG(dst, src) \
    asm volatile("cp.async.cg.shared.global [%0], [%1], 16;" :: "r"(dst), "l"(src))
#define CP_COMMIT() asm volatile("cp.async.commit_group;" ::: "memory")
#define CP_WAIT(n)  asm volatile("cp.async.wait_group %0;" :: "n"(n) : "memory")

__device__ __forceinline__ unsigned packh2(float x, float y) {
    __half2 h = __floats2half2_rn(x, y);
    return *(unsigned*)&h;
}

__device__ __forceinline__ void ldsm4(unsigned& r0, unsigned& r1, unsigned& r2, unsigned& r3,
                                      unsigned a) {
    asm volatile("ldmatrix.sync.aligned.m8n8.x4.shared.b16 {%0,%1,%2,%3}, [%4];"
                 : "=r"(r0), "=r"(r1), "=r"(r2), "=r"(r3) : "r"(a));
}
__device__ __forceinline__ void ldsm4t(unsigned& r0, unsigned& r1, unsigned& r2, unsigned& r3,
                                       unsigned a) {
    asm volatile("ldmatrix.sync.aligned.m8n8.x4.trans.shared.b16 {%0,%1,%2,%3}, [%4];"
                 : "=r"(r0), "=r"(r1), "=r"(r2), "=r"(r3) : "r"(a));
}
__device__ __forceinline__ void mma16816(float* c, const unsigned* a, const unsigned* b) {
    asm volatile(
        "mma.sync.aligned.m16n8k16.row.col.f32.f16.f16.f32 "
        "{%0,%1,%2,%3},{%4,%5,%6,%7},{%8,%9},{%0,%1,%2,%3};"
        : "+f"(c[0]), "+f"(c[1]), "+f"(c[2]), "+f"(c[3])
        : "r"(a[0]), "r"(a[1]), "r"(a[2]), "r"(a[3]), "r"(b[0]), "r"(b[1]));
}

// stage rows x 64 halves (k-major, 128B rows), XOR swizzle; 4 chunks/call
__device__ __forceinline__ void cp_km(unsigned dst, const char* src, size_t rowBytes,
                                      int r, int cg) {
    const char* p = src + (size_t)r * rowBytes + cg * 16;
    unsigned d = dst + r * 128;
#pragma unroll
    for (int j = 0; j < 4; j++) {
        unsigned c = cg + j;
        CP_CG(d + ((c ^ (r & 7)) << 4), p + j * 16);
    }
}

// stage V chunk: 64 k-rows x 128 n-halves (256B rows); 4 of 16 chunks/thread
__device__ __forceinline__ void cp_vrow(unsigned dst, const char* src, size_t rowBytes,
                                        int k, int cg) {
    const char* p = src + (size_t)k * rowBytes + cg * 16;
    unsigned d = dst + k * 256;
#pragma unroll
    for (int j = 0; j < 4; j++) {
        unsigned c = cg + j;
        CP_CG(d + ((c ^ (k & 7)) << 4), p + j * 16);
    }
}

// load A fragments (2x ldsm4) for one ks step
__device__ __forceinline__ void load_afrag(unsigned af[2][4], unsigned sa,
                                           int ks, int wr, int lane) {
    int ch = ks * 2 + (lane >> 4);
#pragma unroll
    for (int mt = 0; mt < 2; mt++) {
        int row = wr * 32 + mt * 16 + (lane & 15);
        ldsm4(af[mt][0], af[mt][1], af[mt][2], af[mt][3],
              sa + row * 128 + ((ch ^ (row & 7)) << 4));
    }
}

// ============================================================================
// Shared NT gemm body: block 128x128, 256 threads, warps 4x2 of 32x64.
// A-fragment double buffering: prefetch A(ks+1), load B(ks), then MMAs(ks).
// ============================================================================
template <typename TC>
__device__ __forceinline__ void gemm_nt_body(
    const char* pa, const char* pb, const float* bias, TC* C,
    int N, int K, float alpha, int bx, int by, unsigned sbase)
{
    int tid = threadIdx.x, warp = tid >> 5, lane = tid & 31;
    int wr = warp & 3, wc = warp >> 2;       // 4x2 warps, warp tile 32x64
    int qr = lane >> 2, rr = lane & 3;
    int r = tid >> 1, cg = (tid & 1) * 4;    // staging role
    size_t rowB = (size_t)K * 2;

    float acc[2][8][4];
#pragma unroll
    for (int mt = 0; mt < 2; mt++)
#pragma unroll
        for (int nt = 0; nt < 8; nt++)
#pragma unroll
            for (int i = 0; i < 4; i++) acc[mt][nt][i] = 0.f;

    const int nIter = K / 64;

    cp_km(sbase, pa, rowB, r, cg);
    cp_km(sbase + SB_OFF, pb, rowB, r, cg);
    CP_COMMIT();
    cp_km(sbase + STG, pa + 128, rowB, r, cg);
    cp_km(sbase + SB_OFF + STG, pb + 128, rowB, r, cg);
    CP_COMMIT();

    for (int it = 0; it < nIter; ++it) {
        if (it + 2 < nIter) {
            int s = (it + 2) % 3;
            cp_km(sbase + s * STG, pa + (size_t)(it + 2) * 128, rowB, r, cg);
            cp_km(sbase + SB_OFF + s * STG, pb + (size_t)(it + 2) * 128, rowB, r, cg);
            CP_COMMIT();
            CP_WAIT(2);
        } else if (it + 1 < nIter) {
            CP_WAIT(1);
        } else {
            CP_WAIT(0);
        }
        __syncthreads();

        unsigned sa = sbase + (it % 3) * STG;
        unsigned sb = sbase + SB_OFF + (it % 3) * STG;

        unsigned af[2][2][4];            // double-buffered A fragments
        load_afrag(af[0], sa, 0, wr, lane);
#pragma unroll
        for (int ks = 0; ks < 4; ks++) {
            int cur = ks & 1;
            if (ks < 3) load_afrag(af[cur ^ 1], sa, ks + 1, wr, lane);
            int ch = ks * 2 + (lane >> 4);
            unsigned bf[8][2];
#pragma unroll
            for (int ng = 0; ng < 4; ng++) {
                int row = wc * 64 + ng * 16 + (lane & 15);
                unsigned r0, r1, r2, r3;
                ldsm4(r0, r1, r2, r3, sb + row * 128 + ((ch ^ (row & 7)) << 4));
                bf[2 * ng][0] = r0; bf[2 * ng][1] = r2;
                bf[2 * ng + 1][0] = r1; bf[2 * ng + 1][1] = r3;
            }
#pragma unroll
            for (int mt = 0; mt < 2; mt++)
#pragma unroll
                for (int nt = 0; nt < 8; nt++)
                    mma16816(acc[mt][nt], af[cur][mt], bf[nt]);
        }
        __syncthreads();
    }

#pragma unroll
    for (int mt = 0; mt < 2; mt++) {
#pragma unroll
        for (int nt = 0; nt < 8; nt++) {
            int row = by * 128 + wr * 32 + mt * 16 + qr;
            int col = bx * 128 + wc * 64 + nt * 8 + rr * 2;
            float b0 = bias ? bias[col] : 0.f;
            float b1 = bias ? bias[col + 1] : 0.f;
            float x0 = acc[mt][nt][0] * alpha + b0;
            float x1 = acc[mt][nt][1] * alpha + b1;
            float x2 = acc[mt][nt][2] * alpha + b0;
            float x3 = acc[mt][nt][3] * alpha + b1;
            if constexpr (sizeof(TC) == 2) {
                *(unsigned*)&C[(size_t)row * N + col] = packh2(x0, x1);
                *(unsigned*)&C[(size_t)(row + 8) * N + col] = packh2(x2, x3);
            } else {
                float2 v;
                v.x = x0; v.y = x1;
                *(float2*)&C[(size_t)row * N + col] = v;
                v.x = x2; v.y = x3;
                *(float2*)&C[(size_t)(row + 8) * N + col] = v;
            }
        }
    }
}

// ============================================================================
// Batched projections: z in {0,1,2} selects (X, W, bias, out). One launch.
// ============================================================================
__global__ __launch_bounds__(256, 2) void hgemm_proj3(
    const __half* __restrict__ X0, const __half* __restrict__ X1,
    const __half* __restrict__ X2,
    const __half* __restrict__ W0, const __half* __restrict__ W1,
    const __half* __restrict__ W2,
    const float* __restrict__ b0, const float* __restrict__ b1,
    const float* __restrict__ b2,
    __half* __restrict__ C0, __half* __restrict__ C1, __half* __restrict__ C2)
{
    extern __shared__ char raw[];
    char* smem = (char*)(((uintptr_t)raw + 1023) & ~(uintptr_t)1023);
    unsigned sbase = (unsigned)__cvta_generic_to_shared(smem);

    int bx = blockIdx.x, by = blockIdx.y, bz = blockIdx.z;
    const __half* X = (bz == 0) ? X0 : (bz == 1) ? X1 : X2;
    const __half* W = (bz == 0) ? W0 : (bz == 1) ? W1 : W2;
    const float* bias = (bz == 0) ? b0 : (bz == 1) ? b1 : b2;
    __half* C = (bz == 0) ? C0 : (bz == 1) ? C1 : C2;

    const char* pa = (const char*)(X + (size_t)(by * 128) * DEMB);
    const char* pb = (const char*)(W + (size_t)(bx * 128) * DEMB);
    gemm_nt_body<__half>(pa, pb, bias, C, DEMB, DEMB, 1.f, bx, by, sbase);
}

// ============================================================================
// QK^T: batched over z, causal block skip. C = f32 S.
// ============================================================================
__global__ __launch_bounds__(256, 2) void hgemm_qk(
    const __half* __restrict__ Q, const __half* __restrict__ Kd,
    float* __restrict__ S, float alpha)
{
    int bx = blockIdx.x, by = blockIdx.y, bz = blockIdx.z;
    if (bx > by) return;

    extern __shared__ char raw[];
    char* smem = (char*)(((uintptr_t)raw + 1023) & ~(uintptr_t)1023);
    unsigned sbase = (unsigned)__cvta_generic_to_shared(smem);

    const char* pa = (const char*)(Q + (size_t)bz * TDIM * DEMB + (size_t)(by * 128) * DEMB);
    const char* pb = (const char*)(Kd + (size_t)bz * TDIM * DEMB + (size_t)(bx * 128) * DEMB);
    float* C = S + (size_t)bz * TDIM * TDIM;
    gemm_nt_body<float>(pa, pb, nullptr, C, TDIM, DEMB, alpha, bx, by, sbase);
}

// ============================================================================
// PV: O[m,n] = sum_k P[m,k]*V[k,n]; block 128x128, warps 4x2 of 32x64.
// A-fragment double buffering mirrors gemm_nt_body.
// ============================================================================
__global__ __launch_bounds__(256, 2) void hgemm_pv(
    const __half* __restrict__ P, const __half* __restrict__ V,
    float* __restrict__ O)
{
    int bx = blockIdx.x, by = blockIdx.y, bz = blockIdx.z;

    extern __shared__ char raw[];
    char* smem = (char*)(((uintptr_t)raw + 1023) & ~(uintptr_t)1023);
    unsigned sbase = (unsigned)__cvta_generic_to_shared(smem);

    int tid = threadIdx.x, warp = tid >> 5, lane = tid & 31;
    int wr = warp & 3, wc = warp >> 2;
    int qr = lane >> 2, rr = lane & 3;
    int r = tid >> 1, cg = (tid & 1) * 4;       // P staging
    int vk = tid >> 2, vg = (tid & 3) * 4;      // V staging: 64 rows, 4 thr/row

    const char* pa = (const char*)(P + (size_t)bz * TDIM * TDIM + (size_t)(by * 128) * TDIM);
    const char* pv = (const char*)(V + (size_t)bz * TDIM * DEMB + bx * 128);
    float* C = O + (size_t)bz * TDIM * DEMB;
    size_t rowA = (size_t)TDIM * 2;
    size_t rowV = (size_t)DEMB * 2;

    float acc[2][8][4];
#pragma unroll
    for (int mt = 0; mt < 2; mt++)
#pragma unroll
        for (int nt = 0; nt < 8; nt++)
#pragma unroll
            for (int i = 0; i < 4; i++) acc[mt][nt][i] = 0.f;

    const int nIter = (by + 1) * 2;   // k up to (by+1)*128, BK=64

    cp_km(sbase, pa, rowA, r, cg);
    cp_vrow(sbase + SB_OFF, pv, rowV, vk, vg);
    CP_COMMIT();
    cp_km(sbase + STG, pa + 128, rowA, r, cg);
    cp_vrow(sbase + SB_OFF + STG, pv + 64 * rowV, rowV, vk, vg);
    CP_COMMIT();

    for (int it = 0; it < nIter; ++it) {
        if (it + 2 < nIter) {
            int s = (it + 2) % 3;
            cp_km(sbase + s * STG, pa + (size_t)(it + 2) * 128, rowA, r, cg);
            cp_vrow(sbase + SB_OFF + s * STG, pv + (size_t)(it + 2) * 64 * rowV, rowV, vk, vg);
            CP_COMMIT();
            CP_WAIT(2);
        } else if (it + 1 < nIter) {
            CP_WAIT(1);
        } else {
            CP_WAIT(0);
        }
        __syncthreads();

        unsigned sa = sbase + (it % 3) * STG;
        unsigned sb = sbase + SB_OFF + (it % 3) * STG;

        unsigned af[2][2][4];
        load_afrag(af[0], sa, 0, wr, lane);
#pragma unroll
        for (int ks = 0; ks < 4; ks++) {
            int cur = ks & 1;
            if (ks < 3) load_afrag(af[cur ^ 1], sa, ks + 1, wr, lane);
            unsigned bf[8][2];
#pragma unroll
            for (int ng = 0; ng < 4; ng++) {
                int krow = ks * 16 + (lane & 15);
                int cb = (wc * 64 + ng * 16) >> 3;
                int vch = cb + (lane >> 4);
                unsigned r0, r1, r2, r3;
                ldsm4t(r0, r1, r2, r3, sb + krow * 256 + ((vch ^ (krow & 7)) << 4));
                bf[2 * ng][0] = r0; bf[2 * ng][1] = r1;
                bf[2 * ng + 1][0] = r2; bf[2 * ng + 1][1] = r3;
            }
#pragma unroll
            for (int mt = 0; mt < 2; mt++)
#pragma unroll
                for (int nt = 0; nt < 8; nt++)
                    mma16816(acc[mt][nt], af[cur][mt], bf[nt]);
        }
        __syncthreads();
    }

#pragma unroll
    for (int mt = 0; mt < 2; mt++) {
#pragma unroll
        for (int nt = 0; nt < 8; nt++) {
            int row = by * 128 + wr * 32 + mt * 16 + qr;
            int col = bx * 128 + wc * 64 + nt * 8 + rr * 2;
            float2 v;
            v.x = acc[mt][nt][0]; v.y = acc[mt][nt][1];
            *(float2*)&C[(size_t)row * DEMB + col] = v;
            v.x = acc[mt][nt][2]; v.y = acc[mt][nt][3];
            *(float2*)&C[(size_t)(row + 8) * DEMB + col] = v;
        }
    }
}

// ---------------------------------------------------------------------------
// Merged f32 -> f16 convert: X triplet (2x ILP) + W triplet folded in.
// ---------------------------------------------------------------------------
__global__ void f2h_all(const float* __restrict__ x0, const float* __restrict__ x1,
                        const float* __restrict__ x2,
                        __half* __restrict__ y0, __half* __restrict__ y1,
                        __half* __restrict__ y2,
                        const float* __restrict__ w0, const float* __restrict__ w1,
                        const float* __restrict__ w2,
                        __half* __restrict__ z0, __half* __restrict__ z1,
                        __half* __restrict__ z2, int nX4, int nW4)
{
    int stride = gridDim.x * blockDim.x;
    int i0 = blockIdx.x * blockDim.x + threadIdx.x;
    if (i0 < nW4) {
        float4 a = *(const float4*)(w0 + (size_t)i0 * 4);
        float4 b = *(const float4*)(w1 + (size_t)i0 * 4);
        float4 c = *(const float4*)(w2 + (size_t)i0 * 4);
        uint2 u;
        u.x = packh2(a.x, a.y); u.y = packh2(a.z, a.w);
        *(uint2*)(z0 + (size_t)i0 * 4) = u;
        u.x = packh2(b.x, b.y); u.y = packh2(b.z, b.w);
        *(uint2*)(z1 + (size_t)i0 * 4) = u;
        u.x = packh2(c.x, c.y); u.y = packh2(c.z, c.w);
        *(uint2*)(z2 + (size_t)i0 * 4) = u;
    }
    for (int i = i0; i < nX4; i += 2 * stride) {
        int i1 = i + stride;
        float4 a0 = *(const float4*)(x0 + (size_t)i * 4);
        float4 b0 = *(const float4*)(x1 + (size_t)i * 4);
        float4 c0 = *(const float4*)(x2 + (size_t)i * 4);
        float4 a1, b1, c1;
        bool has1 = (i1 < nX4);
        if (has1) {
            a1 = *(const float4*)(x0 + (size_t)i1 * 4);
            b1 = *(const float4*)(x1 + (size_t)i1 * 4);
            c1 = *(const float4*)(x2 + (size_t)i1 * 4);
        }
        uint2 u;
        u.x = packh2(a0.x, a0.y); u.y = packh2(a0.z, a0.w);
        *(uint2*)(y0 + (size_t)i * 4) = u;
        u.x = packh2(b0.x, b0.y); u.y = packh2(b0.z, b0.w);
        *(uint2*)(y1 + (size_t)i * 4) = u;
        u.x = packh2(c0.x, c0.y); u.y = packh2(c0.z, c0.w);
        *(uint2*)(y2 + (size_t)i * 4) = u;
        if (has1) {
            u.x = packh2(a1.x, a1.y); u.y = packh2(a1.z, a1.w);
            *(uint2*)(y0 + (size_t)i1 * 4) = u;
            u.x = packh2(b1.x, b1.y); u.y = packh2(b1.z, b1.w);
            *(uint2*)(y1 + (size_t)i1 * 4) = u;
            u.x = packh2(c1.x, c1.y); u.y = packh2(c1.z, c1.w);
            *(uint2*)(y2 + (size_t)i1 * 4) = u;
        }
    }
}

// ---------------------------------------------------------------------------
// Causal softmax: f32 S row -> half P row; zero tail. 256 thr x 4 elems.
// ---------------------------------------------------------------------------
__global__ void softmax_causal(const float* __restrict__ S, __half* __restrict__ P)
{
    int q = blockIdx.x, b = blockIdx.y;
    const float* row = S + ((size_t)b * TDIM + q) * TDIM;
    __half* prow = P + ((size_t)b * TDIM + q) * TDIM;
    int len = q + 1;
    int tid = threadIdx.x;
    int lane = tid & 31, warp = tid >> 5;

    __shared__ float sred[8];

    int i0 = tid * 4;
    float x[4] = {-1e30f, -1e30f, -1e30f, -1e30f};
    if (i0 < len) {
        float4 v = *(const float4*)(row + i0);
        x[0] = v.x; x[1] = v.y; x[2] = v.z; x[3] = v.w;
#pragma unroll
        for (int j = 1; j < 4; j++)
            if (i0 + j >= len) x[j] = -1e30f;
    }

    float m = fmaxf(fmaxf(x[0], x[1]), fmaxf(x[2], x[3]));
#pragma unroll
    for (int o = 16; o; o >>= 1) m = fmaxf(m, __shfl_xor_sync(0xffffffffu, m, o));
    if (lane == 0) sred[warp] = m;
    __syncthreads();
    if (tid < 32) {
        float t = (tid < 8) ? sred[tid] : -1e30f;
#pragma unroll
        for (int o = 4; o; o >>= 1) t = fmaxf(t, __shfl_xor_sync(0xffffffffu, t, o));
        if (tid == 0) sred[0] = t;
    }
    __syncthreads();
    m = sred[0];

    float e[4], sum = 0.f;
#pragma unroll
    for (int j = 0; j < 4; j++) {
        e[j] = (i0 + j < len) ? __expf(x[j] - m) : 0.f;
        sum += e[j];
    }
#pragma unroll
    for (int o = 16; o; o >>= 1) sum += __shfl_xor_sync(0xffffffffu, sum, o);
    if (lane == 0) sred[warp] = sum;
    __syncthreads();
    if (tid < 32) {
        float t = (tid < 8) ? sred[tid] : 0.f;
#pragma unroll
        for (int o = 4; o; o >>= 1) t += __shfl_xor_sync(0xffffffffu, t, o);
        if (tid == 0) sred[0] = t;
    }
    __syncthreads();
    float inv = 1.f / sred[0];

    uint2 u;
    u.x = packh2(e[0] * inv, e[1] * inv);
    u.y = packh2(e[2] * inv, e[3] * inv);
    *(uint2*)(prow + i0) = u;
}

extern "C" void kernel_launch(void* const* d_in, const int* in_sizes, int n_in,
                              void* d_out, int out_size)
{
    const float* qx = (const float*)d_in[0];
    const float* kx = (const float*)d_in[1];
    const float* vx = (const float*)d_in[2];
    const float* Wq = (const float*)d_in[3];
    const float* bq = (const float*)d_in[4];
    const float* Wk = (const float*)d_in[5];
    const float* bk = (const float*)d_in[6];
    const float* Wv = (const float*)d_in[7];
    const float* bv = (const float*)d_in[8];
    float* out = (float*)d_out;

    __half *pQ, *pK, *pV, *pP, *pXq, *pXk, *pXv, *pWq, *pWk, *pWv;
    float* pS;
    cudaGetSymbolAddress((void**)&pQ, g_Q);
    cudaGetSymbolAddress((void**)&pK, g_K);
    cudaGetSymbolAddress((void**)&pV, g_V);
    cudaGetSymbolAddress((void**)&pP, g_P);
    cudaGetSymbolAddress((void**)&pS, g_S);
    cudaGetSymbolAddress((void**)&pXq, g_Xq);
    cudaGetSymbolAddress((void**)&pXk, g_Xk);
    cudaGetSymbolAddress((void**)&pXv, g_Xv);
    cudaGetSymbolAddress((void**)&pWq, g_Wqh);
    cudaGetSymbolAddress((void**)&pWk, g_Wkh);
    cudaGetSymbolAddress((void**)&pWv, g_Wvh);

    cudaFuncSetAttribute(hgemm_proj3,
                         cudaFuncAttributeMaxDynamicSharedMemorySize, SMEM_BYTES);
    cudaFuncSetAttribute(hgemm_qk,
                         cudaFuncAttributeMaxDynamicSharedMemorySize, SMEM_BYTES);
    cudaFuncSetAttribute(hgemm_pv,
                         cudaFuncAttributeMaxDynamicSharedMemorySize, SMEM_BYTES);

    const int NX4 = NB * TDIM * DEMB / 4;   // 4M float4 per X tensor
    const int NW4 = DEMB * DEMB / 4;        // 256K float4 per W tensor
    f2h_all<<<4096, 256>>>(qx, kx, vx, pXq, pXk, pXv,
                           Wq, Wk, Wv, pWq, pWk, pWv, NX4, NW4);

    dim3 blk(256);

    // All three projections in ONE launch (z selects tensor triple)
    dim3 gproj(DEMB / 128, (NB * TDIM) / 128, 3);
    hgemm_proj3<<<gproj, blk, SMEM_BYTES>>>(pXq, pXk, pXv, pWq, pWk, pWv,
                                            bq, bk, bv, pQ, pK, pV);

    // S = Q K^T / 32 (blocks above diagonal skipped)
    dim3 gattn(TDIM / 128, TDIM / 128, NB);
    hgemm_qk<<<gattn, blk, SMEM_BYTES>>>(pQ, pK, pS, 0.03125f);

    // softmax: S (f32) -> P (half), zero tail
    softmax_causal<<<dim3(TDIM, NB), 256>>>(pS, pP);

    // O = P V (k clipped at diagonal)
    hgemm_pv<<<gattn, blk, SMEM_BYTES>>>(pP, pV, out);
}

// round 15
// speedup vs baseline: 1.5798x; 1.1444x over previous
#include <cuda_runtime.h>
#include <cuda_fp16.h>
#include <stdint.h>

#define NB 16
#define TDIM 1024
#define DEMB 1024

// ---------------- scratch (__device__ globals, allocation-free rule) --------
__device__ __half g_Q[(size_t)NB * TDIM * DEMB];
__device__ __half g_K[(size_t)NB * TDIM * DEMB];
__device__ __half g_V[(size_t)NB * TDIM * DEMB];
__device__ __half g_P[(size_t)NB * TDIM * TDIM];
__device__ float  g_S[(size_t)NB * TDIM * TDIM];
__device__ __half g_Xq[(size_t)NB * TDIM * DEMB];
__device__ __half g_Xk[(size_t)NB * TDIM * DEMB];
__device__ __half g_Xv[(size_t)NB * TDIM * DEMB];
__device__ __half g_Wqh[DEMB * DEMB];
__device__ __half g_Wkh[DEMB * DEMB];
__device__ __half g_Wvh[DEMB * DEMB];

// ---------------- smem: 3 stages; A 16KB/stage, B 16KB/stage (96KB) --------
constexpr int STG = 16384;            // 128 rows x 128B (or 64 rows x 256B for V)
constexpr int SB_OFF = 3 * STG;
constexpr int SMEM_BYTES = 6 * STG + 1024;

#define CP_CG(dst, src) \
    asm volatile("cp.async.cg.shared.global [%0], [%1], 16;" :: "r"(dst), "l"(src))
#define CP_COMMIT() asm volatile("cp.async.commit_group;" ::: "memory")
#define CP_WAIT(n)  asm volatile("cp.async.wait_group %0;" :: "n"(n) : "memory")

__device__ __forceinline__ unsigned packh2(float x, float y) {
    __half2 h = __floats2half2_rn(x, y);
    return *(unsigned*)&h;
}

__device__ __forceinline__ void ldsm4(unsigned& r0, unsigned& r1, unsigned& r2, unsigned& r3,
                                      unsigned a) {
    asm volatile("ldmatrix.sync.aligned.m8n8.x4.shared.b16 {%0,%1,%2,%3}, [%4];"
                 : "=r"(r0), "=r"(r1), "=r"(r2), "=r"(r3) : "r"(a));
}
__device__ __forceinline__ void ldsm4t(unsigned& r0, unsigned& r1, unsigned& r2, unsigned& r3,
                                       unsigned a) {
    asm volatile("ldmatrix.sync.aligned.m8n8.x4.trans.shared.b16 {%0,%1,%2,%3}, [%4];"
                 : "=r"(r0), "=r"(r1), "=r"(r2), "=r"(r3) : "r"(a));
}
__device__ __forceinline__ void mma16816(float* c, const unsigned* a, const unsigned* b) {
    asm volatile(
        "mma.sync.aligned.m16n8k16.row.col.f32.f16.f16.f32 "
        "{%0,%1,%2,%3},{%4,%5,%6,%7},{%8,%9},{%0,%1,%2,%3};"
        : "+f"(c[0]), "+f"(c[1]), "+f"(c[2]), "+f"(c[3])
        : "r"(a[0]), "r"(a[1]), "r"(a[2]), "r"(a[3]), "r"(b[0]), "r"(b[1]));
}

// stage rows x 64 halves (k-major, 128B rows), XOR swizzle; 2 chunks/call (512 thr)
__device__ __forceinline__ void cp_km(unsigned dst, const char* src, size_t rowBytes,
                                      int r, int cg) {
    const char* p = src + (size_t)r * rowBytes + cg * 16;
    unsigned d = dst + r * 128;
#pragma unroll
    for (int j = 0; j < 2; j++) {
        unsigned c = cg + j;
        CP_CG(d + ((c ^ (r & 7)) << 4), p + j * 16);
    }
}

// stage V chunk: 64 k-rows x 128 n-halves (256B rows); 2 of 16 chunks/thread
__device__ __forceinline__ void cp_vrow(unsigned dst, const char* src, size_t rowBytes,
                                        int k, int cg) {
    const char* p = src + (size_t)k * rowBytes + cg * 16;
    unsigned d = dst + k * 256;
#pragma unroll
    for (int j = 0; j < 2; j++) {
        unsigned c = cg + j;
        CP_CG(d + ((c ^ (k & 7)) << 4), p + j * 16);
    }
}

// ============================================================================
// Shared NT gemm body: block 128x128, 512 threads, warps 4x4 of 32x32.
// ============================================================================
template <typename TC>
__device__ __forceinline__ void gemm_nt_body(
    const char* pa, const char* pb, const float* bias, TC* C,
    int N, int K, float alpha, int bx, int by, unsigned sbase)
{
    int tid = threadIdx.x, warp = tid >> 5, lane = tid & 31;
    int wr = warp & 3, wc = warp >> 2;       // 4x4 warps, warp tile 32x32
    int qr = lane >> 2, rr = lane & 3;
    int r = tid >> 2, cg = (tid & 3) * 2;    // staging role: 2 chunks/thread
    size_t rowB = (size_t)K * 2;

    float acc[2][4][4];
#pragma unroll
    for (int mt = 0; mt < 2; mt++)
#pragma unroll
        for (int nt = 0; nt < 4; nt++)
#pragma unroll
            for (int i = 0; i < 4; i++) acc[mt][nt][i] = 0.f;

    const int nIter = K / 64;

    cp_km(sbase, pa, rowB, r, cg);
    cp_km(sbase + SB_OFF, pb, rowB, r, cg);
    CP_COMMIT();
    cp_km(sbase + STG, pa + 128, rowB, r, cg);
    cp_km(sbase + SB_OFF + STG, pb + 128, rowB, r, cg);
    CP_COMMIT();

    for (int it = 0; it < nIter; ++it) {
        if (it + 2 < nIter) {
            int s = (it + 2) % 3;
            cp_km(sbase + s * STG, pa + (size_t)(it + 2) * 128, rowB, r, cg);
            cp_km(sbase + SB_OFF + s * STG, pb + (size_t)(it + 2) * 128, rowB, r, cg);
            CP_COMMIT();
            CP_WAIT(2);
        } else if (it + 1 < nIter) {
            CP_WAIT(1);
        } else {
            CP_WAIT(0);
        }
        __syncthreads();

        unsigned sa = sbase + (it % 3) * STG;
        unsigned sb = sbase + SB_OFF + (it % 3) * STG;
#pragma unroll
        for (int ks = 0; ks < 4; ks++) {
            int ch = ks * 2 + (lane >> 4);
            unsigned af[2][4], bf[4][2];
#pragma unroll
            for (int mt = 0; mt < 2; mt++) {
                int row = wr * 32 + mt * 16 + (lane & 15);
                ldsm4(af[mt][0], af[mt][1], af[mt][2], af[mt][3],
                      sa + row * 128 + ((ch ^ (row & 7)) << 4));
            }
#pragma unroll
            for (int ng = 0; ng < 2; ng++) {
                int row = wc * 32 + ng * 16 + (lane & 15);
                unsigned r0, r1, r2, r3;
                ldsm4(r0, r1, r2, r3, sb + row * 128 + ((ch ^ (row & 7)) << 4));
                bf[2 * ng][0] = r0; bf[2 * ng][1] = r2;
                bf[2 * ng + 1][0] = r1; bf[2 * ng + 1][1] = r3;
            }
#pragma unroll
            for (int mt = 0; mt < 2; mt++)
#pragma unroll
                for (int nt = 0; nt < 4; nt++)
                    mma16816(acc[mt][nt], af[mt], bf[nt]);
        }
        __syncthreads();
    }

#pragma unroll
    for (int mt = 0; mt < 2; mt++) {
#pragma unroll
        for (int nt = 0; nt < 4; nt++) {
            int row = by * 128 + wr * 32 + mt * 16 + qr;
            int col = bx * 128 + wc * 32 + nt * 8 + rr * 2;
            float b0 = bias ? bias[col] : 0.f;
            float b1 = bias ? bias[col + 1] : 0.f;
            float x0 = acc[mt][nt][0] * alpha + b0;
            float x1 = acc[mt][nt][1] * alpha + b1;
            float x2 = acc[mt][nt][2] * alpha + b0;
            float x3 = acc[mt][nt][3] * alpha + b1;
            if constexpr (sizeof(TC) == 2) {
                *(unsigned*)&C[(size_t)row * N + col] = packh2(x0, x1);
                *(unsigned*)&C[(size_t)(row + 8) * N + col] = packh2(x2, x3);
            } else {
                float2 v;
                v.x = x0; v.y = x1;
                *(float2*)&C[(size_t)row * N + col] = v;
                v.x = x2; v.y = x3;
                *(float2*)&C[(size_t)(row + 8) * N + col] = v;
            }
        }
    }
}

// ============================================================================
// Batched projections: z in {0,1,2} selects (X, W, bias, out). One launch.
// ============================================================================
__global__ __launch_bounds__(512, 2) void hgemm_proj3(
    const __half* __restrict__ X0, const __half* __restrict__ X1,
    const __half* __restrict__ X2,
    const __half* __restrict__ W0, const __half* __restrict__ W1,
    const __half* __restrict__ W2,
    const float* __restrict__ b0, const float* __restrict__ b1,
    const float* __restrict__ b2,
    __half* __restrict__ C0, __half* __restrict__ C1, __half* __restrict__ C2)
{
    extern __shared__ char raw[];
    char* smem = (char*)(((uintptr_t)raw + 1023) & ~(uintptr_t)1023);
    unsigned sbase = (unsigned)__cvta_generic_to_shared(smem);

    int bx = blockIdx.x, by = blockIdx.y, bz = blockIdx.z;
    const __half* X = (bz == 0) ? X0 : (bz == 1) ? X1 : X2;
    const __half* W = (bz == 0) ? W0 : (bz == 1) ? W1 : W2;
    const float* bias = (bz == 0) ? b0 : (bz == 1) ? b1 : b2;
    __half* C = (bz == 0) ? C0 : (bz == 1) ? C1 : C2;

    const char* pa = (const char*)(X + (size_t)(by * 128) * DEMB);
    const char* pb = (const char*)(W + (size_t)(bx * 128) * DEMB);
    gemm_nt_body<__half>(pa, pb, bias, C, DEMB, DEMB, 1.f, bx, by, sbase);
}

// ============================================================================
// QK^T: batched over z, causal block skip. C = f32 S.
// ============================================================================
__global__ __launch_bounds__(512, 2) void hgemm_qk(
    const __half* __restrict__ Q, const __half* __restrict__ Kd,
    float* __restrict__ S, float alpha)
{
    int bx = blockIdx.x, by = blockIdx.y, bz = blockIdx.z;
    if (bx > by) return;

    extern __shared__ char raw[];
    char* smem = (char*)(((uintptr_t)raw + 1023) & ~(uintptr_t)1023);
    unsigned sbase = (unsigned)__cvta_generic_to_shared(smem);

    const char* pa = (const char*)(Q + (size_t)bz * TDIM * DEMB + (size_t)(by * 128) * DEMB);
    const char* pb = (const char*)(Kd + (size_t)bz * TDIM * DEMB + (size_t)(bx * 128) * DEMB);
    float* C = S + (size_t)bz * TDIM * TDIM;
    gemm_nt_body<float>(pa, pb, nullptr, C, TDIM, DEMB, alpha, bx, by, sbase);
}

// ============================================================================
// PV: O[m,n] = sum_k P[m,k]*V[k,n]; block 128x128, 512 thr, warps 4x4 of 32x32.
// P half k-major; V half row-major [k][n] staged 64x256B. k clipped at diag.
// ============================================================================
__global__ __launch_bounds__(512, 2) void hgemm_pv(
    const __half* __restrict__ P, const __half* __restrict__ V,
    float* __restrict__ O)
{
    int bx = blockIdx.x, by = blockIdx.y, bz = blockIdx.z;

    extern __shared__ char raw[];
    char* smem = (char*)(((uintptr_t)raw + 1023) & ~(uintptr_t)1023);
    unsigned sbase = (unsigned)__cvta_generic_to_shared(smem);

    int tid = threadIdx.x, warp = tid >> 5, lane = tid & 31;
    int wr = warp & 3, wc = warp >> 2;
    int qr = lane >> 2, rr = lane & 3;
    int r = tid >> 2, cg = (tid & 3) * 2;       // P staging: 2 chunks/thread
    int vk = tid >> 3, vg = (tid & 7) * 2;      // V staging: 64 rows, 8 thr/row

    const char* pa = (const char*)(P + (size_t)bz * TDIM * TDIM + (size_t)(by * 128) * TDIM);
    const char* pv = (const char*)(V + (size_t)bz * TDIM * DEMB + bx * 128);
    float* C = O + (size_t)bz * TDIM * DEMB;
    size_t rowA = (size_t)TDIM * 2;
    size_t rowV = (size_t)DEMB * 2;

    float acc[2][4][4];
#pragma unroll
    for (int mt = 0; mt < 2; mt++)
#pragma unroll
        for (int nt = 0; nt < 4; nt++)
#pragma unroll
            for (int i = 0; i < 4; i++) acc[mt][nt][i] = 0.f;

    const int nIter = (by + 1) * 2;   // k up to (by+1)*128, BK=64

    cp_km(sbase, pa, rowA, r, cg);
    cp_vrow(sbase + SB_OFF, pv, rowV, vk, vg);
    CP_COMMIT();
    cp_km(sbase + STG, pa + 128, rowA, r, cg);
    cp_vrow(sbase + SB_OFF + STG, pv + 64 * rowV, rowV, vk, vg);
    CP_COMMIT();

    for (int it = 0; it < nIter; ++it) {
        if (it + 2 < nIter) {
            int s = (it + 2) % 3;
            cp_km(sbase + s * STG, pa + (size_t)(it + 2) * 128, rowA, r, cg);
            cp_vrow(sbase + SB_OFF + s * STG, pv + (size_t)(it + 2) * 64 * rowV, rowV, vk, vg);
            CP_COMMIT();
            CP_WAIT(2);
        } else if (it + 1 < nIter) {
            CP_WAIT(1);
        } else {
            CP_WAIT(0);
        }
        __syncthreads();

        unsigned sa = sbase + (it % 3) * STG;
        unsigned sb = sbase + SB_OFF + (it % 3) * STG;
#pragma unroll
        for (int ks = 0; ks < 4; ks++) {
            int ch = ks * 2 + (lane >> 4);
            unsigned af[2][4], bf[4][2];
#pragma unroll
            for (int mt = 0; mt < 2; mt++) {
                int row = wr * 32 + mt * 16 + (lane & 15);
                ldsm4(af[mt][0], af[mt][1], af[mt][2], af[mt][3],
                      sa + row * 128 + ((ch ^ (row & 7)) << 4));
            }
#pragma unroll
            for (int ng = 0; ng < 2; ng++) {
                int krow = ks * 16 + (lane & 15);
                int cb = (wc * 32 + ng * 16) >> 3;
                int vch = cb + (lane >> 4);
                unsigned r0, r1, r2, r3;
                ldsm4t(r0, r1, r2, r3, sb + krow * 256 + ((vch ^ (krow & 7)) << 4));
                bf[2 * ng][0] = r0; bf[2 * ng][1] = r1;
                bf[2 * ng + 1][0] = r2; bf[2 * ng + 1][1] = r3;
            }
#pragma unroll
            for (int mt = 0; mt < 2; mt++)
#pragma unroll
                for (int nt = 0; nt < 4; nt++)
                    mma16816(acc[mt][nt], af[mt], bf[nt]);
        }
        __syncthreads();
    }

#pragma unroll
    for (int mt = 0; mt < 2; mt++) {
#pragma unroll
        for (int nt = 0; nt < 4; nt++) {
            int row = by * 128 + wr * 32 + mt * 16 + qr;
            int col = bx * 128 + wc * 32 + nt * 8 + rr * 2;
            float2 v;
            v.x = acc[mt][nt][0]; v.y = acc[mt][nt][1];
            *(float2*)&C[(size_t)row * DEMB + col] = v;
            v.x = acc[mt][nt][2]; v.y = acc[mt][nt][3];
            *(float2*)&C[(size_t)(row + 8) * DEMB + col] = v;
        }
    }
}

// ---------------------------------------------------------------------------
// Merged f32 -> f16 convert: X triplet (2x ILP) + W triplet folded in.
// ---------------------------------------------------------------------------
__global__ void f2h_all(const float* __restrict__ x0, const float* __restrict__ x1,
                        const float* __restrict__ x2,
                        __half* __restrict__ y0, __half* __restrict__ y1,
                        __half* __restrict__ y2,
                        const float* __restrict__ w0, const float* __restrict__ w1,
                        const float* __restrict__ w2,
                        __half* __restrict__ z0, __half* __restrict__ z1,
                        __half* __restrict__ z2, int nX4, int nW4)
{
    int stride = gridDim.x * blockDim.x;
    int i0 = blockIdx.x * blockDim.x + threadIdx.x;
    if (i0 < nW4) {
        float4 a = *(const float4*)(w0 + (size_t)i0 * 4);
        float4 b = *(const float4*)(w1 + (size_t)i0 * 4);
        float4 c = *(const float4*)(w2 + (size_t)i0 * 4);
        uint2 u;
        u.x = packh2(a.x, a.y); u.y = packh2(a.z, a.w);
        *(uint2*)(z0 + (size_t)i0 * 4) = u;
        u.x = packh2(b.x, b.y); u.y = packh2(b.z, b.w);
        *(uint2*)(z1 + (size_t)i0 * 4) = u;
        u.x = packh2(c.x, c.y); u.y = packh2(c.z, c.w);
        *(uint2*)(z2 + (size_t)i0 * 4) = u;
    }
    for (int i = i0; i < nX4; i += 2 * stride) {
        int i1 = i + stride;
        float4 a0 = *(const float4*)(x0 + (size_t)i * 4);
        float4 b0 = *(const float4*)(x1 + (size_t)i * 4);
        float4 c0 = *(const float4*)(x2 + (size_t)i * 4);
        float4 a1, b1, c1;
        bool has1 = (i1 < nX4);
        if (has1) {
            a1 = *(const float4*)(x0 + (size_t)i1 * 4);
            b1 = *(const float4*)(x1 + (size_t)i1 * 4);
            c1 = *(const float4*)(x2 + (size_t)i1 * 4);
        }
        uint2 u;
        u.x = packh2(a0.x, a0.y); u.y = packh2(a0.z, a0.w);
        *(uint2*)(y0 + (size_t)i * 4) = u;
        u.x = packh2(b0.x, b0.y); u.y = packh2(b0.z, b0.w);
        *(uint2*)(y1 + (size_t)i * 4) = u;
        u.x = packh2(c0.x, c0.y); u.y = packh2(c0.z, c0.w);
        *(uint2*)(y2 + (size_t)i * 4) = u;
        if (has1) {
            u.x = packh2(a1.x, a1.y); u.y = packh2(a1.z, a1.w);
            *(uint2*)(y0 + (size_t)i1 * 4) = u;
            u.x = packh2(b1.x, b1.y); u.y = packh2(b1.z, b1.w);
            *(uint2*)(y1 + (size_t)i1 * 4) = u;
            u.x = packh2(c1.x, c1.y); u.y = packh2(c1.z, c1.w);
            *(uint2*)(y2 + (size_t)i1 * 4) = u;
        }
    }
}

// ---------------------------------------------------------------------------
// Causal softmax: f32 S row -> half P row; zero tail. 256 thr x 4 elems.
// ---------------------------------------------------------------------------
__global__ void softmax_causal(const float* __restrict__ S, __half* __restrict__ P)
{
    int q = blockIdx.x, b = blockIdx.y;
    const float* row = S + ((size_t)b * TDIM + q) * TDIM;
    __half* prow = P + ((size_t)b * TDIM + q) * TDIM;
    int len = q + 1;
    int tid = threadIdx.x;
    int lane = tid & 31, warp = tid >> 5;

    __shared__ float sred[8];

    int i0 = tid * 4;
    float x[4] = {-1e30f, -1e30f, -1e30f, -1e30f};
    if (i0 < len) {
        float4 v = *(const float4*)(row + i0);
        x[0] = v.x; x[1] = v.y; x[2] = v.z; x[3] = v.w;
#pragma unroll
        for (int j = 1; j < 4; j++)
            if (i0 + j >= len) x[j] = -1e30f;
    }

    float m = fmaxf(fmaxf(x[0], x[1]), fmaxf(x[2], x[3]));
#pragma unroll
    for (int o = 16; o; o >>= 1) m = fmaxf(m, __shfl_xor_sync(0xffffffffu, m, o));
    if (lane == 0) sred[warp] = m;
    __syncthreads();
    if (tid < 32) {
        float t = (tid < 8) ? sred[tid] : -1e30f;
#pragma unroll
        for (int o = 4; o; o >>= 1) t = fmaxf(t, __shfl_xor_sync(0xffffffffu, t, o));
        if (tid == 0) sred[0] = t;
    }
    __syncthreads();
    m = sred[0];

    float e[4], sum = 0.f;
#pragma unroll
    for (int j = 0; j < 4; j++) {
        e[j] = (i0 + j < len) ? __expf(x[j] - m) : 0.f;
        sum += e[j];
    }
#pragma unroll
    for (int o = 16; o; o >>= 1) sum += __shfl_xor_sync(0xffffffffu, sum, o);
    if (lane == 0) sred[warp] = sum;
    __syncthreads();
    if (tid < 32) {
        float t = (tid < 8) ? sred[tid] : 0.f;
#pragma unroll
        for (int o = 4; o; o >>= 1) t += __shfl_xor_sync(0xffffffffu, t, o);
        if (tid == 0) sred[0] = t;
    }
    __syncthreads();
    float inv = 1.f / sred[0];

    uint2 u;
    u.x = packh2(e[0] * inv, e[1] * inv);
    u.y = packh2(e[2] * inv, e[3] * inv);
    *(uint2*)(prow + i0) = u;
}

extern "C" void kernel_launch(void* const* d_in, const int* in_sizes, int n_in,
                              void* d_out, int out_size)
{
    const float* qx = (const float*)d_in[0];
    const float* kx = (const float*)d_in[1];
    const float* vx = (const float*)d_in[2];
    const float* Wq = (const float*)d_in[3];
    const float* bq = (const float*)d_in[4];
    const float* Wk = (const float*)d_in[5];
    const float* bk = (const float*)d_in[6];
    const float* Wv = (const float*)d_in[7];
    const float* bv = (const float*)d_in[8];
    float* out = (float*)d_out;

    __half *pQ, *pK, *pV, *pP, *pXq, *pXk, *pXv, *pWq, *pWk, *pWv;
    float* pS;
    cudaGetSymbolAddress((void**)&pQ, g_Q);
    cudaGetSymbolAddress((void**)&pK, g_K);
    cudaGetSymbolAddress((void**)&pV, g_V);
    cudaGetSymbolAddress((void**)&pP, g_P);
    cudaGetSymbolAddress((void**)&pS, g_S);
    cudaGetSymbolAddress((void**)&pXq, g_Xq);
    cudaGetSymbolAddress((void**)&pXk, g_Xk);
    cudaGetSymbolAddress((void**)&pXv, g_Xv);
    cudaGetSymbolAddress((void**)&pWq, g_Wqh);
    cudaGetSymbolAddress((void**)&pWk, g_Wkh);
    cudaGetSymbolAddress((void**)&pWv, g_Wvh);

    cudaFuncSetAttribute(hgemm_proj3,
                         cudaFuncAttributeMaxDynamicSharedMemorySize, SMEM_BYTES);
    cudaFuncSetAttribute(hgemm_qk,
                         cudaFuncAttributeMaxDynamicSharedMemorySize, SMEM_BYTES);
    cudaFuncSetAttribute(hgemm_pv,
                         cudaFuncAttributeMaxDynamicSharedMemorySize, SMEM_BYTES);

    const int NX4 = NB * TDIM * DEMB / 4;   // 4M float4 per X tensor
    const int NW4 = DEMB * DEMB / 4;        // 256K float4 per W tensor
    f2h_all<<<4096, 256>>>(qx, kx, vx, pXq, pXk, pXv,
                           Wq, Wk, Wv, pWq, pWk, pWv, NX4, NW4);

    dim3 blk(512);

    // All three projections in ONE launch (z selects tensor triple)
    dim3 gproj(DEMB / 128, (NB * TDIM) / 128, 3);
    hgemm_proj3<<<gproj, blk, SMEM_BYTES>>>(pXq, pXk, pXv, pWq, pWk, pWv,
                                            bq, bk, bv, pQ, pK, pV);

    // S = Q K^T / 32 (blocks above diagonal skipped)
    dim3 gattn(TDIM / 128, TDIM / 128, NB);
    hgemm_qk<<<gattn, blk, SMEM_BYTES>>>(pQ, pK, pS, 0.03125f);

    // softmax: S (f32) -> P (half), zero tail
    softmax_causal<<<dim3(TDIM, NB), 256>>>(pS, pP);

    // O = P V (k clipped at diagonal)
    hgemm_pv<<<gattn, blk, SMEM_BYTES>>>(pP, pV, out);
}

// round 16
// speedup vs baseline: 1.6173x; 1.0237x over previous
#include <cuda_runtime.h>
#include <cuda_fp16.h>
#include <stdint.h>

#define NB 16
#define TDIM 1024
#define DEMB 1024

// ---------------- scratch (__device__ globals, allocation-free rule) --------
__device__ __half g_Q[(size_t)NB * TDIM * DEMB];
__device__ __half g_K[(size_t)NB * TDIM * DEMB];
__device__ __half g_V[(size_t)NB * TDIM * DEMB];
__device__ __half g_P[(size_t)NB * TDIM * TDIM];
__device__ float  g_S[(size_t)NB * TDIM * TDIM];
__device__ __half g_Xq[(size_t)NB * TDIM * DEMB];
__device__ __half g_Xk[(size_t)NB * TDIM * DEMB];
__device__ __half g_Xv[(size_t)NB * TDIM * DEMB];
__device__ __half g_Wqh[DEMB * DEMB];
__device__ __half g_Wkh[DEMB * DEMB];
__device__ __half g_Wvh[DEMB * DEMB];

// ---------------- smem: 3 stages; A 16KB/stage, B 16KB/stage (96KB) --------
constexpr int STG = 16384;            // 128 rows x 128B (or 64 rows x 256B for V)
constexpr int SB_OFF = 3 * STG;
constexpr int SMEM_BYTES = 6 * STG + 1024;

#define CP_CG(dst, src) \
    asm volatile("cp.async.cg.shared.global [%0], [%1], 16;" :: "r"(dst), "l"(src))
#define CP_COMMIT() asm volatile("cp.async.commit_group;" ::: "memory")
#define CP_WAIT(n)  asm volatile("cp.async.wait_group %0;" :: "n"(n) : "memory")

__device__ __forceinline__ unsigned packh2(float x, float y) {
    __half2 h = __floats2half2_rn(x, y);
    return *(unsigned*)&h;
}

__device__ __forceinline__ void ldsm4(unsigned& r0, unsigned& r1, unsigned& r2, unsigned& r3,
                                      unsigned a) {
    asm volatile("ldmatrix.sync.aligned.m8n8.x4.shared.b16 {%0,%1,%2,%3}, [%4];"
                 : "=r"(r0), "=r"(r1), "=r"(r2), "=r"(r3) : "r"(a));
}
__device__ __forceinline__ void ldsm4t(unsigned& r0, unsigned& r1, unsigned& r2, unsigned& r3,
                                       unsigned a) {
    asm volatile("ldmatrix.sync.aligned.m8n8.x4.trans.shared.b16 {%0,%1,%2,%3}, [%4];"
                 : "=r"(r0), "=r"(r1), "=r"(r2), "=r"(r3) : "r"(a));
}
__device__ __forceinline__ void mma16816(float* c, const unsigned* a, const unsigned* b) {
    asm volatile(
        "mma.sync.aligned.m16n8k16.row.col.f32.f16.f16.f32 "
        "{%0,%1,%2,%3},{%4,%5,%6,%7},{%8,%9},{%0,%1,%2,%3};"
        : "+f"(c[0]), "+f"(c[1]), "+f"(c[2]), "+f"(c[3])
        : "r"(a[0]), "r"(a[1]), "r"(a[2]), "r"(a[3]), "r"(b[0]), "r"(b[1]));
}

// stage rows x 64 halves (k-major, 128B rows), XOR swizzle; 2 chunks/call (512 thr)
__device__ __forceinline__ void cp_km(unsigned dst, const char* src, size_t rowBytes,
                                      int r, int cg) {
    const char* p = src + (size_t)r * rowBytes + cg * 16;
    unsigned d = dst + r * 128;
#pragma unroll
    for (int j = 0; j < 2; j++) {
        unsigned c = cg + j;
        CP_CG(d + ((c ^ (r & 7)) << 4), p + j * 16);
    }
}

// stage V chunk: 64 k-rows x 128 n-halves (256B rows); 2 of 16 chunks/thread
__device__ __forceinline__ void cp_vrow(unsigned dst, const char* src, size_t rowBytes,
                                        int k, int cg) {
    const char* p = src + (size_t)k * rowBytes + cg * 16;
    unsigned d = dst + k * 256;
#pragma unroll
    for (int j = 0; j < 2; j++) {
        unsigned c = cg + j;
        CP_CG(d + ((c ^ (k & 7)) << 4), p + j * 16);
    }
}

// ============================================================================
// Shared NT gemm body: block 128x128, 512 threads, warps 4x4 of 32x32.
// ============================================================================
template <typename TC>
__device__ __forceinline__ void gemm_nt_body(
    const char* pa, const char* pb, const float* bias, TC* C,
    int N, int K, float alpha, int bx, int by, unsigned sbase)
{
    int tid = threadIdx.x, warp = tid >> 5, lane = tid & 31;
    int wr = warp & 3, wc = warp >> 2;       // 4x4 warps, warp tile 32x32
    int qr = lane >> 2, rr = lane & 3;
    int r = tid >> 2, cg = (tid & 3) * 2;    // staging role: 2 chunks/thread
    size_t rowB = (size_t)K * 2;

    float acc[2][4][4];
#pragma unroll
    for (int mt = 0; mt < 2; mt++)
#pragma unroll
        for (int nt = 0; nt < 4; nt++)
#pragma unroll
            for (int i = 0; i < 4; i++) acc[mt][nt][i] = 0.f;

    const int nIter = K / 64;

    cp_km(sbase, pa, rowB, r, cg);
    cp_km(sbase + SB_OFF, pb, rowB, r, cg);
    CP_COMMIT();
    cp_km(sbase + STG, pa + 128, rowB, r, cg);
    cp_km(sbase + SB_OFF + STG, pb + 128, rowB, r, cg);
    CP_COMMIT();

    for (int it = 0; it < nIter; ++it) {
        if (it + 2 < nIter) {
            int s = (it + 2) % 3;
            cp_km(sbase + s * STG, pa + (size_t)(it + 2) * 128, rowB, r, cg);
            cp_km(sbase + SB_OFF + s * STG, pb + (size_t)(it + 2) * 128, rowB, r, cg);
            CP_COMMIT();
            CP_WAIT(2);
        } else if (it + 1 < nIter) {
            CP_WAIT(1);
        } else {
            CP_WAIT(0);
        }
        __syncthreads();

        unsigned sa = sbase + (it % 3) * STG;
        unsigned sb = sbase + SB_OFF + (it % 3) * STG;
#pragma unroll
        for (int ks = 0; ks < 4; ks++) {
            int ch = ks * 2 + (lane >> 4);
            unsigned af[2][4], bf[4][2];
#pragma unroll
            for (int mt = 0; mt < 2; mt++) {
                int row = wr * 32 + mt * 16 + (lane & 15);
                ldsm4(af[mt][0], af[mt][1], af[mt][2], af[mt][3],
                      sa + row * 128 + ((ch ^ (row & 7)) << 4));
            }
#pragma unroll
            for (int ng = 0; ng < 2; ng++) {
                int row = wc * 32 + ng * 16 + (lane & 15);
                unsigned r0, r1, r2, r3;
                ldsm4(r0, r1, r2, r3, sb + row * 128 + ((ch ^ (row & 7)) << 4));
                bf[2 * ng][0] = r0; bf[2 * ng][1] = r2;
                bf[2 * ng + 1][0] = r1; bf[2 * ng + 1][1] = r3;
            }
#pragma unroll
            for (int mt = 0; mt < 2; mt++)
#pragma unroll
                for (int nt = 0; nt < 4; nt++)
                    mma16816(acc[mt][nt], af[mt], bf[nt]);
        }
        __syncthreads();
    }

#pragma unroll
    for (int mt = 0; mt < 2; mt++) {
#pragma unroll
        for (int nt = 0; nt < 4; nt++) {
            int row = by * 128 + wr * 32 + mt * 16 + qr;
            int col = bx * 128 + wc * 32 + nt * 8 + rr * 2;
            float b0 = bias ? bias[col] : 0.f;
            float b1 = bias ? bias[col + 1] : 0.f;
            float x0 = acc[mt][nt][0] * alpha + b0;
            float x1 = acc[mt][nt][1] * alpha + b1;
            float x2 = acc[mt][nt][2] * alpha + b0;
            float x3 = acc[mt][nt][3] * alpha + b1;
            if constexpr (sizeof(TC) == 2) {
                *(unsigned*)&C[(size_t)row * N + col] = packh2(x0, x1);
                *(unsigned*)&C[(size_t)(row + 8) * N + col] = packh2(x2, x3);
            } else {
                float2 v;
                v.x = x0; v.y = x1;
                *(float2*)&C[(size_t)row * N + col] = v;
                v.x = x2; v.y = x3;
                *(float2*)&C[(size_t)(row + 8) * N + col] = v;
            }
        }
    }
}

// ============================================================================
// Batched projections: z in {0,1,2} selects (X, W, bias, out). One launch.
// ============================================================================
__global__ __launch_bounds__(512, 2) void hgemm_proj3(
    const __half* __restrict__ X0, const __half* __restrict__ X1,
    const __half* __restrict__ X2,
    const __half* __restrict__ W0, const __half* __restrict__ W1,
    const __half* __restrict__ W2,
    const float* __restrict__ b0, const float* __restrict__ b1,
    const float* __restrict__ b2,
    __half* __restrict__ C0, __half* __restrict__ C1, __half* __restrict__ C2)
{
    extern __shared__ char raw[];
    char* smem = (char*)(((uintptr_t)raw + 1023) & ~(uintptr_t)1023);
    unsigned sbase = (unsigned)__cvta_generic_to_shared(smem);

    int bx = blockIdx.x, by = blockIdx.y, bz = blockIdx.z;
    const __half* X = (bz == 0) ? X0 : (bz == 1) ? X1 : X2;
    const __half* W = (bz == 0) ? W0 : (bz == 1) ? W1 : W2;
    const float* bias = (bz == 0) ? b0 : (bz == 1) ? b1 : b2;
    __half* C = (bz == 0) ? C0 : (bz == 1) ? C1 : C2;

    const char* pa = (const char*)(X + (size_t)(by * 128) * DEMB);
    const char* pb = (const char*)(W + (size_t)(bx * 128) * DEMB);
    gemm_nt_body<__half>(pa, pb, bias, C, DEMB, DEMB, 1.f, bx, by, sbase);
}

// ============================================================================
// QK^T: compacted lower-triangle grid (36 blocks/batch). C = f32 S.
// blockIdx.x = triangular index t -> (by, bx) with bx <= by.
// ============================================================================
__global__ __launch_bounds__(512, 2) void hgemm_qk(
    const __half* __restrict__ Q, const __half* __restrict__ Kd,
    float* __restrict__ S, float alpha)
{
    int t = blockIdx.x, bz = blockIdx.z;
    // decode triangular index: by = largest n with n(n+1)/2 <= t
    int by = (int)((sqrtf(8.f * t + 1.f) - 1.f) * 0.5f);
    while ((by + 1) * (by + 2) / 2 <= t) by++;
    while (by * (by + 1) / 2 > t) by--;
    int bx = t - by * (by + 1) / 2;

    extern __shared__ char raw[];
    char* smem = (char*)(((uintptr_t)raw + 1023) & ~(uintptr_t)1023);
    unsigned sbase = (unsigned)__cvta_generic_to_shared(smem);

    const char* pa = (const char*)(Q + (size_t)bz * TDIM * DEMB + (size_t)(by * 128) * DEMB);
    const char* pb = (const char*)(Kd + (size_t)bz * TDIM * DEMB + (size_t)(bx * 128) * DEMB);
    float* C = S + (size_t)bz * TDIM * TDIM;
    gemm_nt_body<float>(pa, pb, nullptr, C, TDIM, DEMB, alpha, bx, by, sbase);
}

// ============================================================================
// PV: O[m,n] = sum_k P[m,k]*V[k,n]; heavy-first by ordering (by reversed).
// ============================================================================
__global__ __launch_bounds__(512, 2) void hgemm_pv(
    const __half* __restrict__ P, const __half* __restrict__ V,
    float* __restrict__ O)
{
    int bx = blockIdx.x, bz = blockIdx.z;
    int by = (gridDim.y - 1) - blockIdx.y;   // heavy blocks dispatched first

    extern __shared__ char raw[];
    char* smem = (char*)(((uintptr_t)raw + 1023) & ~(uintptr_t)1023);
    unsigned sbase = (unsigned)__cvta_generic_to_shared(smem);

    int tid = threadIdx.x, warp = tid >> 5, lane = tid & 31;
    int wr = warp & 3, wc = warp >> 2;
    int qr = lane >> 2, rr = lane & 3;
    int r = tid >> 2, cg = (tid & 3) * 2;       // P staging: 2 chunks/thread
    int vk = tid >> 3, vg = (tid & 7) * 2;      // V staging: 64 rows, 8 thr/row

    const char* pa = (const char*)(P + (size_t)bz * TDIM * TDIM + (size_t)(by * 128) * TDIM);
    const char* pv = (const char*)(V + (size_t)bz * TDIM * DEMB + bx * 128);
    float* C = O + (size_t)bz * TDIM * DEMB;
    size_t rowA = (size_t)TDIM * 2;
    size_t rowV = (size_t)DEMB * 2;

    float acc[2][4][4];
#pragma unroll
    for (int mt = 0; mt < 2; mt++)
#pragma unroll
        for (int nt = 0; nt < 4; nt++)
#pragma unroll
            for (int i = 0; i < 4; i++) acc[mt][nt][i] = 0.f;

    const int nIter = (by + 1) * 2;   // k up to (by+1)*128, BK=64

    cp_km(sbase, pa, rowA, r, cg);
    cp_vrow(sbase + SB_OFF, pv, rowV, vk, vg);
    CP_COMMIT();
    cp_km(sbase + STG, pa + 128, rowA, r, cg);
    cp_vrow(sbase + SB_OFF + STG, pv + 64 * rowV, rowV, vk, vg);
    CP_COMMIT();

    for (int it = 0; it < nIter; ++it) {
        if (it + 2 < nIter) {
            int s = (it + 2) % 3;
            cp_km(sbase + s * STG, pa + (size_t)(it + 2) * 128, rowA, r, cg);
            cp_vrow(sbase + SB_OFF + s * STG, pv + (size_t)(it + 2) * 64 * rowV, rowV, vk, vg);
            CP_COMMIT();
            CP_WAIT(2);
        } else if (it + 1 < nIter) {
            CP_WAIT(1);
        } else {
            CP_WAIT(0);
        }
        __syncthreads();

        unsigned sa = sbase + (it % 3) * STG;
        unsigned sb = sbase + SB_OFF + (it % 3) * STG;
#pragma unroll
        for (int ks = 0; ks < 4; ks++) {
            int ch = ks * 2 + (lane >> 4);
            unsigned af[2][4], bf[4][2];
#pragma unroll
            for (int mt = 0; mt < 2; mt++) {
                int row = wr * 32 + mt * 16 + (lane & 15);
                ldsm4(af[mt][0], af[mt][1], af[mt][2], af[mt][3],
                      sa + row * 128 + ((ch ^ (row & 7)) << 4));
            }
#pragma unroll
            for (int ng = 0; ng < 2; ng++) {
                int krow = ks * 16 + (lane & 15);
                int cb = (wc * 32 + ng * 16) >> 3;
                int vch = cb + (lane >> 4);
                unsigned r0, r1, r2, r3;
                ldsm4t(r0, r1, r2, r3, sb + krow * 256 + ((vch ^ (krow & 7)) << 4));
                bf[2 * ng][0] = r0; bf[2 * ng][1] = r1;
                bf[2 * ng + 1][0] = r2; bf[2 * ng + 1][1] = r3;
            }
#pragma unroll
            for (int mt = 0; mt < 2; mt++)
#pragma unroll
                for (int nt = 0; nt < 4; nt++)
                    mma16816(acc[mt][nt], af[mt], bf[nt]);
        }
        __syncthreads();
    }

#pragma unroll
    for (int mt = 0; mt < 2; mt++) {
#pragma unroll
        for (int nt = 0; nt < 4; nt++) {
            int row = by * 128 + wr * 32 + mt * 16 + qr;
            int col = bx * 128 + wc * 32 + nt * 8 + rr * 2;
            float2 v;
            v.x = acc[mt][nt][0]; v.y = acc[mt][nt][1];
            *(float2*)&C[(size_t)row * DEMB + col] = v;
            v.x = acc[mt][nt][2]; v.y = acc[mt][nt][3];
            *(float2*)&C[(size_t)(row + 8) * DEMB + col] = v;
        }
    }
}

// ---------------------------------------------------------------------------
// Merged f32 -> f16 convert: X triplet (2x ILP) + W triplet folded in.
// ---------------------------------------------------------------------------
__global__ void f2h_all(const float* __restrict__ x0, const float* __restrict__ x1,
                        const float* __restrict__ x2,
                        __half* __restrict__ y0, __half* __restrict__ y1,
                        __half* __restrict__ y2,
                        const float* __restrict__ w0, const float* __restrict__ w1,
                        const float* __restrict__ w2,
                        __half* __restrict__ z0, __half* __restrict__ z1,
                        __half* __restrict__ z2, int nX4, int nW4)
{
    int stride = gridDim.x * blockDim.x;
    int i0 = blockIdx.x * blockDim.x + threadIdx.x;
    if (i0 < nW4) {
        float4 a = *(const float4*)(w0 + (size_t)i0 * 4);
        float4 b = *(const float4*)(w1 + (size_t)i0 * 4);
        float4 c = *(const float4*)(w2 + (size_t)i0 * 4);
        uint2 u;
        u.x = packh2(a.x, a.y); u.y = packh2(a.z, a.w);
        *(uint2*)(z0 + (size_t)i0 * 4) = u;
        u.x = packh2(b.x, b.y); u.y = packh2(b.z, b.w);
        *(uint2*)(z1 + (size_t)i0 * 4) = u;
        u.x = packh2(c.x, c.y); u.y = packh2(c.z, c.w);
        *(uint2*)(z2 + (size_t)i0 * 4) = u;
    }
    for (int i = i0; i < nX4; i += 2 * stride) {
        int i1 = i + stride;
        float4 a0 = *(const float4*)(x0 + (size_t)i * 4);
        float4 b0 = *(const float4*)(x1 + (size_t)i * 4);
        float4 c0 = *(const float4*)(x2 + (size_t)i * 4);
        float4 a1, b1, c1;
        bool has1 = (i1 < nX4);
        if (has1) {
            a1 = *(const float4*)(x0 + (size_t)i1 * 4);
            b1 = *(const float4*)(x1 + (size_t)i1 * 4);
            c1 = *(const float4*)(x2 + (size_t)i1 * 4);
        }
        uint2 u;
        u.x = packh2(a0.x, a0.y); u.y = packh2(a0.z, a0.w);
        *(uint2*)(y0 + (size_t)i * 4) = u;
        u.x = packh2(b0.x, b0.y); u.y = packh2(b0.z, b0.w);
        *(uint2*)(y1 + (size_t)i * 4) = u;
        u.x = packh2(c0.x, c0.y); u.y = packh2(c0.z, c0.w);
        *(uint2*)(y2 + (size_t)i * 4) = u;
        if (has1) {
            u.x = packh2(a1.x, a1.y); u.y = packh2(a1.z, a1.w);
            *(uint2*)(y0 + (size_t)i1 * 4) = u;
            u.x = packh2(b1.x, b1.y); u.y = packh2(b1.z, b1.w);
            *(uint2*)(y1 + (size_t)i1 * 4) = u;
            u.x = packh2(c1.x, c1.y); u.y = packh2(c1.z, c1.w);
            *(uint2*)(y2 + (size_t)i1 * 4) = u;
        }
    }
}

// ---------------------------------------------------------------------------
// Causal softmax: f32 S row -> half P row; zero tail. 256 thr x 4 elems.
// ---------------------------------------------------------------------------
__global__ void softmax_causal(const float* __restrict__ S, __half* __restrict__ P)
{
    int q = blockIdx.x, b = blockIdx.y;
    const float* row = S + ((size_t)b * TDIM + q) * TDIM;
    __half* prow = P + ((size_t)b * TDIM + q) * TDIM;
    int len = q + 1;
    int tid = threadIdx.x;
    int lane = tid & 31, warp = tid >> 5;

    __shared__ float sred[8];

    int i0 = tid * 4;
    float x[4] = {-1e30f, -1e30f, -1e30f, -1e30f};
    if (i0 < len) {
        float4 v = *(const float4*)(row + i0);
        x[0] = v.x; x[1] = v.y; x[2] = v.z; x[3] = v.w;
#pragma unroll
        for (int j = 1; j < 4; j++)
            if (i0 + j >= len) x[j] = -1e30f;
    }

    float m = fmaxf(fmaxf(x[0], x[1]), fmaxf(x[2], x[3]));
#pragma unroll
    for (int o = 16; o; o >>= 1) m = fmaxf(m, __shfl_xor_sync(0xffffffffu, m, o));
    if (lane == 0) sred[warp] = m;
    __syncthreads();
    if (tid < 32) {
        float t = (tid < 8) ? sred[tid] : -1e30f;
#pragma unroll
        for (int o = 4; o; o >>= 1) t = fmaxf(t, __shfl_xor_sync(0xffffffffu, t, o));
        if (tid == 0) sred[0] = t;
    }
    __syncthreads();
    m = sred[0];

    float e[4], sum = 0.f;
#pragma unroll
    for (int j = 0; j < 4; j++) {
        e[j] = (i0 + j < len) ? __expf(x[j] - m) : 0.f;
        sum += e[j];
    }
#pragma unroll
    for (int o = 16; o; o >>= 1) sum += __shfl_xor_sync(0xffffffffu, sum, o);
    if (lane == 0) sred[warp] = sum;
    __syncthreads();
    if (tid < 32) {
        float t = (tid < 8) ? sred[tid] : 0.f;
#pragma unroll
        for (int o = 4; o; o >>= 1) t += __shfl_xor_sync(0xffffffffu, t, o);
        if (tid == 0) sred[0] = t;
    }
    __syncthreads();
    float inv = 1.f / sred[0];

    uint2 u;
    u.x = packh2(e[0] * inv, e[1] * inv);
    u.y = packh2(e[2] * inv, e[3] * inv);
    *(uint2*)(prow + i0) = u;
}

extern "C" void kernel_launch(void* const* d_in, const int* in_sizes, int n_in,
                              void* d_out, int out_size)
{
    const float* qx = (const float*)d_in[0];
    const float* kx = (const float*)d_in[1];
    const float* vx = (const float*)d_in[2];
    const float* Wq = (const float*)d_in[3];
    const float* bq = (const float*)d_in[4];
    const float* Wk = (const float*)d_in[5];
    const float* bk = (const float*)d_in[6];
    const float* Wv = (const float*)d_in[7];
    const float* bv = (const float*)d_in[8];
    float* out = (float*)d_out;

    __half *pQ, *pK, *pV, *pP, *pXq, *pXk, *pXv, *pWq, *pWk, *pWv;
    float* pS;
    cudaGetSymbolAddress((void**)&pQ, g_Q);
    cudaGetSymbolAddress((void**)&pK, g_K);
    cudaGetSymbolAddress((void**)&pV, g_V);
    cudaGetSymbolAddress((void**)&pP, g_P);
    cudaGetSymbolAddress((void**)&pS, g_S);
    cudaGetSymbolAddress((void**)&pXq, g_Xq);
    cudaGetSymbolAddress((void**)&pXk, g_Xk);
    cudaGetSymbolAddress((void**)&pXv, g_Xv);
    cudaGetSymbolAddress((void**)&pWq, g_Wqh);
    cudaGetSymbolAddress((void**)&pWk, g_Wkh);
    cudaGetSymbolAddress((void**)&pWv, g_Wvh);

    cudaFuncSetAttribute(hgemm_proj3,
                         cudaFuncAttributeMaxDynamicSharedMemorySize, SMEM_BYTES);
    cudaFuncSetAttribute(hgemm_qk,
                         cudaFuncAttributeMaxDynamicSharedMemorySize, SMEM_BYTES);
    cudaFuncSetAttribute(hgemm_pv,
                         cudaFuncAttributeMaxDynamicSharedMemorySize, SMEM_BYTES);

    const int NX4 = NB * TDIM * DEMB / 4;   // 4M float4 per X tensor
    const int NW4 = DEMB * DEMB / 4;        // 256K float4 per W tensor
    f2h_all<<<8192, 256>>>(qx, kx, vx, pXq, pXk, pXv,
                           Wq, Wk, Wv, pWq, pWk, pWv, NX4, NW4);

    dim3 blk(512);

    // All three projections in ONE launch (z selects tensor triple)
    dim3 gproj(DEMB / 128, (NB * TDIM) / 128, 3);
    hgemm_proj3<<<gproj, blk, SMEM_BYTES>>>(pXq, pXk, pXv, pWq, pWk, pWv,
                                            bq, bk, bv, pQ, pK, pV);

    // S = Q K^T / 32: compacted lower-triangle grid (36 blocks per batch)
    dim3 gqk(36, 1, NB);
    hgemm_qk<<<gqk, blk, SMEM_BYTES>>>(pQ, pK, pS, 0.03125f);

    // softmax: S (f32) -> P (half), zero tail
    softmax_causal<<<dim3(TDIM, NB), 256>>>(pS, pP);

    // O = P V (k clipped at diagonal, heavy-first ordering)
    dim3 gpv(TDIM / 128, TDIM / 128, NB);
    hgemm_pv<<<gpv, blk, SMEM_BYTES>>>(pP, pV, out);
}

// round 17
// speedup vs baseline: 1.6678x; 1.0312x over previous
#include <cuda_runtime.h>
#include <cuda_fp16.h>
#include <stdint.h>

#define NB 16
#define TDIM 1024
#define DEMB 1024

// ---------------- scratch (__device__ globals, allocation-free rule) --------
__device__ __half g_Q[(size_t)NB * TDIM * DEMB];
__device__ __half g_K[(size_t)NB * TDIM * DEMB];
__device__ __half g_V[(size_t)NB * TDIM * DEMB];
__device__ __half g_P[(size_t)NB * TDIM * TDIM];
__device__ float  g_S[(size_t)NB * TDIM * TDIM];
__device__ __half g_Xq[(size_t)NB * TDIM * DEMB];
__device__ __half g_Xk[(size_t)NB * TDIM * DEMB];
__device__ __half g_Xv[(size_t)NB * TDIM * DEMB];
__device__ __half g_Wqh[DEMB * DEMB];
__device__ __half g_Wkh[DEMB * DEMB];
__device__ __half g_Wvh[DEMB * DEMB];

// ---------------- smem: 3 stages; A 16KB/stage, B 16KB/stage (96KB) --------
constexpr int STG = 16384;            // 128 rows x 128B (or 64 rows x 256B for V)
constexpr int SB_OFF = 3 * STG;
constexpr int SMEM_BYTES = 6 * STG + 1024;

#define CP_CG(dst, src) \
    asm volatile("cp.async.cg.shared.global [%0], [%1], 16;" :: "r"(dst), "l"(src))
#define CP_COMMIT() asm volatile("cp.async.commit_group;" ::: "memory")
#define CP_WAIT(n)  asm volatile("cp.async.wait_group %0;" :: "n"(n) : "memory")

__device__ __forceinline__ unsigned packh2(float x, float y) {
    __half2 h = __floats2half2_rn(x, y);
    return *(unsigned*)&h;
}

__device__ __forceinline__ void ldsm4(unsigned& r0, unsigned& r1, unsigned& r2, unsigned& r3,
                                      unsigned a) {
    asm volatile("ldmatrix.sync.aligned.m8n8.x4.shared.b16 {%0,%1,%2,%3}, [%4];"
                 : "=r"(r0), "=r"(r1), "=r"(r2), "=r"(r3) : "r"(a));
}
__device__ __forceinline__ void ldsm4t(unsigned& r0, unsigned& r1, unsigned& r2, unsigned& r3,
                                       unsigned a) {
    asm volatile("ldmatrix.sync.aligned.m8n8.x4.trans.shared.b16 {%0,%1,%2,%3}, [%4];"
                 : "=r"(r0), "=r"(r1), "=r"(r2), "=r"(r3) : "r"(a));
}
__device__ __forceinline__ void mma16816(float* c, const unsigned* a, const unsigned* b) {
    asm volatile(
        "mma.sync.aligned.m16n8k16.row.col.f32.f16.f16.f32 "
        "{%0,%1,%2,%3},{%4,%5,%6,%7},{%8,%9},{%0,%1,%2,%3};"
        : "+f"(c[0]), "+f"(c[1]), "+f"(c[2]), "+f"(c[3])
        : "r"(a[0]), "r"(a[1]), "r"(a[2]), "r"(a[3]), "r"(b[0]), "r"(b[1]));
}

// stage rows x 64 halves (k-major, 128B rows), XOR swizzle; 2 chunks/call (512 thr)
__device__ __forceinline__ void cp_km(unsigned dst, const char* src, size_t rowBytes,
                                      int r, int cg) {
    const char* p = src + (size_t)r * rowBytes + cg * 16;
    unsigned d = dst + r * 128;
#pragma unroll
    for (int j = 0; j < 2; j++) {
        unsigned c = cg + j;
        CP_CG(d + ((c ^ (r & 7)) << 4), p + j * 16);
    }
}

// stage V chunk: 64 k-rows x 128 n-halves (256B rows); 2 of 16 chunks/thread
__device__ __forceinline__ void cp_vrow(unsigned dst, const char* src, size_t rowBytes,
                                        int k, int cg) {
    const char* p = src + (size_t)k * rowBytes + cg * 16;
    unsigned d = dst + k * 256;
#pragma unroll
    for (int j = 0; j < 2; j++) {
        unsigned c = cg + j;
        CP_CG(d + ((c ^ (k & 7)) << 4), p + j * 16);
    }
}

// ============================================================================
// Shared NT gemm body: block 128x128, 512 threads, warps 4x4 of 32x32.
// ONE __syncthreads per k-iteration: WAIT -> sync -> compute -> stage+commit.
// Staging at iter it writes stage (it+2)%3 == (it-1)%3, whose readers
// (compute at it-1) are ordered by the top sync of iter it.
// ============================================================================
template <typename TC>
__device__ __forceinline__ void gemm_nt_body(
    const char* pa, const char* pb, const float* bias, TC* C,
    int N, int K, float alpha, int bx, int by, unsigned sbase)
{
    int tid = threadIdx.x, warp = tid >> 5, lane = tid & 31;
    int wr = warp & 3, wc = warp >> 2;       // 4x4 warps, warp tile 32x32
    int qr = lane >> 2, rr = lane & 3;
    int r = tid >> 2, cg = (tid & 3) * 2;    // staging role: 2 chunks/thread
    size_t rowB = (size_t)K * 2;

    float acc[2][4][4];
#pragma unroll
    for (int mt = 0; mt < 2; mt++)
#pragma unroll
        for (int nt = 0; nt < 4; nt++)
#pragma unroll
            for (int i = 0; i < 4; i++) acc[mt][nt][i] = 0.f;

    const int nIter = K / 64;

    cp_km(sbase, pa, rowB, r, cg);
    cp_km(sbase + SB_OFF, pb, rowB, r, cg);
    CP_COMMIT();
    cp_km(sbase + STG, pa + 128, rowB, r, cg);
    cp_km(sbase + SB_OFF + STG, pb + 128, rowB, r, cg);
    CP_COMMIT();

    for (int it = 0; it < nIter; ++it) {
        if (it + 1 < nIter) { CP_WAIT(1); } else { CP_WAIT(0); }
        __syncthreads();

        unsigned sa = sbase + (it % 3) * STG;
        unsigned sb = sbase + SB_OFF + (it % 3) * STG;
#pragma unroll
        for (int ks = 0; ks < 4; ks++) {
            int ch = ks * 2 + (lane >> 4);
            unsigned af[2][4], bf[4][2];
#pragma unroll
            for (int mt = 0; mt < 2; mt++) {
                int row = wr * 32 + mt * 16 + (lane & 15);
                ldsm4(af[mt][0], af[mt][1], af[mt][2], af[mt][3],
                      sa + row * 128 + ((ch ^ (row & 7)) << 4));
            }
#pragma unroll
            for (int ng = 0; ng < 2; ng++) {
                int row = wc * 32 + ng * 16 + (lane & 15);
                unsigned r0, r1, r2, r3;
                ldsm4(r0, r1, r2, r3, sb + row * 128 + ((ch ^ (row & 7)) << 4));
                bf[2 * ng][0] = r0; bf[2 * ng][1] = r2;
                bf[2 * ng + 1][0] = r1; bf[2 * ng + 1][1] = r3;
            }
#pragma unroll
            for (int mt = 0; mt < 2; mt++)
#pragma unroll
                for (int nt = 0; nt < 4; nt++)
                    mma16816(acc[mt][nt], af[mt], bf[nt]);
        }

        if (it + 2 < nIter) {
            int s = (it + 2) % 3;
            cp_km(sbase + s * STG, pa + (size_t)(it + 2) * 128, rowB, r, cg);
            cp_km(sbase + SB_OFF + s * STG, pb + (size_t)(it + 2) * 128, rowB, r, cg);
            CP_COMMIT();
        }
    }

#pragma unroll
    for (int mt = 0; mt < 2; mt++) {
#pragma unroll
        for (int nt = 0; nt < 4; nt++) {
            int row = by * 128 + wr * 32 + mt * 16 + qr;
            int col = bx * 128 + wc * 32 + nt * 8 + rr * 2;
            float b0 = bias ? bias[col] : 0.f;
            float b1 = bias ? bias[col + 1] : 0.f;
            float x0 = acc[mt][nt][0] * alpha + b0;
            float x1 = acc[mt][nt][1] * alpha + b1;
            float x2 = acc[mt][nt][2] * alpha + b0;
            float x3 = acc[mt][nt][3] * alpha + b1;
            if constexpr (sizeof(TC) == 2) {
                *(unsigned*)&C[(size_t)row * N + col] = packh2(x0, x1);
                *(unsigned*)&C[(size_t)(row + 8) * N + col] = packh2(x2, x3);
            } else {
                float2 v;
                v.x = x0; v.y = x1;
                *(float2*)&C[(size_t)row * N + col] = v;
                v.x = x2; v.y = x3;
                *(float2*)&C[(size_t)(row + 8) * N + col] = v;
            }
        }
    }
}

// ============================================================================
// Batched projections: z in {0,1,2} selects (X, W, bias, out). One launch.
// ============================================================================
__global__ __launch_bounds__(512, 2) void hgemm_proj3(
    const __half* __restrict__ X0, const __half* __restrict__ X1,
    const __half* __restrict__ X2,
    const __half* __restrict__ W0, const __half* __restrict__ W1,
    const __half* __restrict__ W2,
    const float* __restrict__ b0, const float* __restrict__ b1,
    const float* __restrict__ b2,
    __half* __restrict__ C0, __half* __restrict__ C1, __half* __restrict__ C2)
{
    extern __shared__ char raw[];
    char* smem = (char*)(((uintptr_t)raw + 1023) & ~(uintptr_t)1023);
    unsigned sbase = (unsigned)__cvta_generic_to_shared(smem);

    int bx = blockIdx.x, by = blockIdx.y, bz = blockIdx.z;
    const __half* X = (bz == 0) ? X0 : (bz == 1) ? X1 : X2;
    const __half* W = (bz == 0) ? W0 : (bz == 1) ? W1 : W2;
    const float* bias = (bz == 0) ? b0 : (bz == 1) ? b1 : b2;
    __half* C = (bz == 0) ? C0 : (bz == 1) ? C1 : C2;

    const char* pa = (const char*)(X + (size_t)(by * 128) * DEMB);
    const char* pb = (const char*)(W + (size_t)(bx * 128) * DEMB);
    gemm_nt_body<__half>(pa, pb, bias, C, DEMB, DEMB, 1.f, bx, by, sbase);
}

// ============================================================================
// QK^T: compacted lower-triangle grid (36 blocks/batch). C = f32 S.
// ============================================================================
__global__ __launch_bounds__(512, 2) void hgemm_qk(
    const __half* __restrict__ Q, const __half* __restrict__ Kd,
    float* __restrict__ S, float alpha)
{
    int t = blockIdx.x, bz = blockIdx.z;
    int by = (int)((sqrtf(8.f * t + 1.f) - 1.f) * 0.5f);
    while ((by + 1) * (by + 2) / 2 <= t) by++;
    while (by * (by + 1) / 2 > t) by--;
    int bx = t - by * (by + 1) / 2;

    extern __shared__ char raw[];
    char* smem = (char*)(((uintptr_t)raw + 1023) & ~(uintptr_t)1023);
    unsigned sbase = (unsigned)__cvta_generic_to_shared(smem);

    const char* pa = (const char*)(Q + (size_t)bz * TDIM * DEMB + (size_t)(by * 128) * DEMB);
    const char* pb = (const char*)(Kd + (size_t)bz * TDIM * DEMB + (size_t)(bx * 128) * DEMB);
    float* C = S + (size_t)bz * TDIM * TDIM;
    gemm_nt_body<float>(pa, pb, nullptr, C, TDIM, DEMB, alpha, bx, by, sbase);
}

// ============================================================================
// PV: O[m,n] = sum_k P[m,k]*V[k,n]; heavy-first by ordering; one-sync loop.
// ============================================================================
__global__ __launch_bounds__(512, 2) void hgemm_pv(
    const __half* __restrict__ P, const __half* __restrict__ V,
    float* __restrict__ O)
{
    int bx = blockIdx.x, bz = blockIdx.z;
    int by = (gridDim.y - 1) - blockIdx.y;

    extern __shared__ char raw[];
    char* smem = (char*)(((uintptr_t)raw + 1023) & ~(uintptr_t)1023);
    unsigned sbase = (unsigned)__cvta_generic_to_shared(smem);

    int tid = threadIdx.x, warp = tid >> 5, lane = tid & 31;
    int wr = warp & 3, wc = warp >> 2;
    int qr = lane >> 2, rr = lane & 3;
    int r = tid >> 2, cg = (tid & 3) * 2;       // P staging: 2 chunks/thread
    int vk = tid >> 3, vg = (tid & 7) * 2;      // V staging: 64 rows, 8 thr/row

    const char* pa = (const char*)(P + (size_t)bz * TDIM * TDIM + (size_t)(by * 128) * TDIM);
    const char* pv = (const char*)(V + (size_t)bz * TDIM * DEMB + bx * 128);
    float* C = O + (size_t)bz * TDIM * DEMB;
    size_t rowA = (size_t)TDIM * 2;
    size_t rowV = (size_t)DEMB * 2;

    float acc[2][4][4];
#pragma unroll
    for (int mt = 0; mt < 2; mt++)
#pragma unroll
        for (int nt = 0; nt < 4; nt++)
#pragma unroll
            for (int i = 0; i < 4; i++) acc[mt][nt][i] = 0.f;

    const int nIter = (by + 1) * 2;

    cp_km(sbase, pa, rowA, r, cg);
    cp_vrow(sbase + SB_OFF, pv, rowV, vk, vg);
    CP_COMMIT();
    cp_km(sbase + STG, pa + 128, rowA, r, cg);
    cp_vrow(sbase + SB_OFF + STG, pv + 64 * rowV, rowV, vk, vg);
    CP_COMMIT();

    for (int it = 0; it < nIter; ++it) {
        if (it + 1 < nIter) { CP_WAIT(1); } else { CP_WAIT(0); }
        __syncthreads();

        unsigned sa = sbase + (it % 3) * STG;
        unsigned sb = sbase + SB_OFF + (it % 3) * STG;
#pragma unroll
        for (int ks = 0; ks < 4; ks++) {
            int ch = ks * 2 + (lane >> 4);
            unsigned af[2][4], bf[4][2];
#pragma unroll
            for (int mt = 0; mt < 2; mt++) {
                int row = wr * 32 + mt * 16 + (lane & 15);
                ldsm4(af[mt][0], af[mt][1], af[mt][2], af[mt][3],
                      sa + row * 128 + ((ch ^ (row & 7)) << 4));
            }
#pragma unroll
            for (int ng = 0; ng < 2; ng++) {
                int krow = ks * 16 + (lane & 15);
                int cb = (wc * 32 + ng * 16) >> 3;
                int vch = cb + (lane >> 4);
                unsigned r0, r1, r2, r3;
                ldsm4t(r0, r1, r2, r3, sb + krow * 256 + ((vch ^ (krow & 7)) << 4));
                bf[2 * ng][0] = r0; bf[2 * ng][1] = r1;
                bf[2 * ng + 1][0] = r2; bf[2 * ng + 1][1] = r3;
            }
#pragma unroll
            for (int mt = 0; mt < 2; mt++)
#pragma unroll
                for (int nt = 0; nt < 4; nt++)
                    mma16816(acc[mt][nt], af[mt], bf[nt]);
        }

        if (it + 2 < nIter) {
            int s = (it + 2) % 3;
            cp_km(sbase + s * STG, pa + (size_t)(it + 2) * 128, rowA, r, cg);
            cp_vrow(sbase + SB_OFF + s * STG, pv + (size_t)(it + 2) * 64 * rowV, rowV, vk, vg);
            CP_COMMIT();
        }
    }

#pragma unroll
    for (int mt = 0; mt < 2; mt++) {
#pragma unroll
        for (int nt = 0; nt < 4; nt++) {
            int row = by * 128 + wr * 32 + mt * 16 + qr;
            int col = bx * 128 + wc * 32 + nt * 8 + rr * 2;
            float2 v;
            v.x = acc[mt][nt][0]; v.y = acc[mt][nt][1];
            *(float2*)&C[(size_t)row * DEMB + col] = v;
            v.x = acc[mt][nt][2]; v.y = acc[mt][nt][3];
            *(float2*)&C[(size_t)(row + 8) * DEMB + col] = v;
        }
    }
}

// ---------------------------------------------------------------------------
// Merged f32 -> f16 convert: X triplet (2x ILP) + W triplet folded in.
// ---------------------------------------------------------------------------
__global__ void f2h_all(const float* __restrict__ x0, const float* __restrict__ x1,
                        const float* __restrict__ x2,
                        __half* __restrict__ y0, __half* __restrict__ y1,
                        __half* __restrict__ y2,
                        const float* __restrict__ w0, const float* __restrict__ w1,
                        const float* __restrict__ w2,
                        __half* __restrict__ z0, __half* __restrict__ z1,
                        __half* __restrict__ z2, int nX4, int nW4)
{
    int stride = gridDim.x * blockDim.x;
    int i0 = blockIdx.x * blockDim.x + threadIdx.x;
    if (i0 < nW4) {
        float4 a = *(const float4*)(w0 + (size_t)i0 * 4);
        float4 b = *(const float4*)(w1 + (size_t)i0 * 4);
        float4 c = *(const float4*)(w2 + (size_t)i0 * 4);
        uint2 u;
        u.x = packh2(a.x, a.y); u.y = packh2(a.z, a.w);
        *(uint2*)(z0 + (size_t)i0 * 4) = u;
        u.x = packh2(b.x, b.y); u.y = packh2(b.z, b.w);
        *(uint2*)(z1 + (size_t)i0 * 4) = u;
        u.x = packh2(c.x, c.y); u.y = packh2(c.z, c.w);
        *(uint2*)(z2 + (size_t)i0 * 4) = u;
    }
    for (int i = i0; i < nX4; i += 2 * stride) {
        int i1 = i + stride;
        float4 a0 = *(const float4*)(x0 + (size_t)i * 4);
        float4 b0 = *(const float4*)(x1 + (size_t)i * 4);
        float4 c0 = *(const float4*)(x2 + (size_t)i * 4);
        float4 a1, b1, c1;
        bool has1 = (i1 < nX4);
        if (has1) {
            a1 = *(const float4*)(x0 + (size_t)i1 * 4);
            b1 = *(const float4*)(x1 + (size_t)i1 * 4);
            c1 = *(const float4*)(x2 + (size_t)i1 * 4);
        }
        uint2 u;
        u.x = packh2(a0.x, a0.y); u.y = packh2(a0.z, a0.w);
        *(uint2*)(y0 + (size_t)i * 4) = u;
        u.x = packh2(b0.x, b0.y); u.y = packh2(b0.z, b0.w);
        *(uint2*)(y1 + (size_t)i * 4) = u;
        u.x = packh2(c0.x, c0.y); u.y = packh2(c0.z, c0.w);
        *(uint2*)(y2 + (size_t)i * 4) = u;
        if (has1) {
            u.x = packh2(a1.x, a1.y); u.y = packh2(a1.z, a1.w);
            *(uint2*)(y0 + (size_t)i1 * 4) = u;
            u.x = packh2(b1.x, b1.y); u.y = packh2(b1.z, b1.w);
            *(uint2*)(y1 + (size_t)i1 * 4) = u;
            u.x = packh2(c1.x, c1.y); u.y = packh2(c1.z, c1.w);
            *(uint2*)(y2 + (size_t)i1 * 4) = u;
        }
    }
}

// ---------------------------------------------------------------------------
// Causal softmax: f32 S row -> half P row; zero tail. 256 thr x 4 elems.
// ---------------------------------------------------------------------------
__global__ void softmax_causal(const float* __restrict__ S, __half* __restrict__ P)
{
    int q = blockIdx.x, b = blockIdx.y;
    const float* row = S + ((size_t)b * TDIM + q) * TDIM;
    __half* prow = P + ((size_t)b * TDIM + q) * TDIM;
    int len = q + 1;
    int tid = threadIdx.x;
    int lane = tid & 31, warp = tid >> 5;

    __shared__ float sred[8];

    int i0 = tid * 4;
    float x[4] = {-1e30f, -1e30f, -1e30f, -1e30f};
    if (i0 < len) {
        float4 v = *(const float4*)(row + i0);
        x[0] = v.x; x[1] = v.y; x[2] = v.z; x[3] = v.w;
#pragma unroll
        for (int j = 1; j < 4; j++)
            if (i0 + j >= len) x[j] = -1e30f;
    }

    float m = fmaxf(fmaxf(x[0], x[1]), fmaxf(x[2], x[3]));
#pragma unroll
    for (int o = 16; o; o >>= 1) m = fmaxf(m, __shfl_xor_sync(0xffffffffu, m, o));
    if (lane == 0) sred[warp] = m;
    __syncthreads();
    if (tid < 32) {
        float t = (tid < 8) ? sred[tid] : -1e30f;
#pragma unroll
        for (int o = 4; o; o >>= 1) t = fmaxf(t, __shfl_xor_sync(0xffffffffu, t, o));
        if (tid == 0) sred[0] = t;
    }
    __syncthreads();
    m = sred[0];

    float e[4], sum = 0.f;
#pragma unroll
    for (int j = 0; j < 4; j++) {
        e[j] = (i0 + j < len) ? __expf(x[j] - m) : 0.f;
        sum += e[j];
    }
#pragma unroll
    for (int o = 16; o; o >>= 1) sum += __shfl_xor_sync(0xffffffffu, sum, o);
    if (lane == 0) sred[warp] = sum;
    __syncthreads();
    if (tid < 32) {
        float t = (tid < 8) ? sred[tid] : 0.f;
#pragma unroll
        for (int o = 4; o; o >>= 1) t += __shfl_xor_sync(0xffffffffu, t, o);
        if (tid == 0) sred[0] = t;
    }
    __syncthreads();
    float inv = 1.f / sred[0];

    uint2 u;
    u.x = packh2(e[0] * inv, e[1] * inv);
    u.y = packh2(e[2] * inv, e[3] * inv);
    *(uint2*)(prow + i0) = u;
}

extern "C" void kernel_launch(void* const* d_in, const int* in_sizes, int n_in,
                              void* d_out, int out_size)
{
    const float* qx = (const float*)d_in[0];
    const float* kx = (const float*)d_in[1];
    const float* vx = (const float*)d_in[2];
    const float* Wq = (const float*)d_in[3];
    const float* bq = (const float*)d_in[4];
    const float* Wk = (const float*)d_in[5];
    const float* bk = (const float*)d_in[6];
    const float* Wv = (const float*)d_in[7];
    const float* bv = (const float*)d_in[8];
    float* out = (float*)d_out;

    __half *pQ, *pK, *pV, *pP, *pXq, *pXk, *pXv, *pWq, *pWk, *pWv;
    float* pS;
    cudaGetSymbolAddress((void**)&pQ, g_Q);
    cudaGetSymbolAddress((void**)&pK, g_K);
    cudaGetSymbolAddress((void**)&pV, g_V);
    cudaGetSymbolAddress((void**)&pP, g_P);
    cudaGetSymbolAddress((void**)&pS, g_S);
    cudaGetSymbolAddress((void**)&pXq, g_Xq);
    cudaGetSymbolAddress((void**)&pXk, g_Xk);
    cudaGetSymbolAddress((void**)&pXv, g_Xv);
    cudaGetSymbolAddress((void**)&pWq, g_Wqh);
    cudaGetSymbolAddress((void**)&pWk, g_Wkh);
    cudaGetSymbolAddress((void**)&pWv, g_Wvh);

    cudaFuncSetAttribute(hgemm_proj3,
                         cudaFuncAttributeMaxDynamicSharedMemorySize, SMEM_BYTES);
    cudaFuncSetAttribute(hgemm_qk,
                         cudaFuncAttributeMaxDynamicSharedMemorySize, SMEM_BYTES);
    cudaFuncSetAttribute(hgemm_pv,
                         cudaFuncAttributeMaxDynamicSharedMemorySize, SMEM_BYTES);

    const int NX4 = NB * TDIM * DEMB / 4;   // 4M float4 per X tensor
    const int NW4 = DEMB * DEMB / 4;        // 256K float4 per W tensor
    f2h_all<<<8192, 256>>>(qx, kx, vx, pXq, pXk, pXv,
                           Wq, Wk, Wv, pWq, pWk, pWv, NX4, NW4);

    dim3 blk(512);

    // All three projections in ONE launch (z selects tensor triple)
    dim3 gproj(DEMB / 128, (NB * TDIM) / 128, 3);
    hgemm_proj3<<<gproj, blk, SMEM_BYTES>>>(pXq, pXk, pXv, pWq, pWk, pWv,
                                            bq, bk, bv, pQ, pK, pV);

    // S = Q K^T / 32: compacted lower-triangle grid (36 blocks per batch)
    dim3 gqk(36, 1, NB);
    hgemm_qk<<<gqk, blk, SMEM_BYTES>>>(pQ, pK, pS, 0.03125f);

    // softmax: S (f32) -> P (half), zero tail
    softmax_causal<<<dim3(TDIM, NB), 256>>>(pS, pP);

    // O = P V (k clipped at diagonal, heavy-first ordering)
    dim3 gpv(TDIM / 128, TDIM / 128, NB);
    hgemm_pv<<<gpv, blk, SMEM_BYTES>>>(pP, pV, out);
}